// round 11
// baseline (speedup 1.0000x reference)
#include <cuda_runtime.h>

#define WDIM  64
#define SDIM  512
#define C8    64
#define ROWST 516   // row-major phase stride (words)
#define FGST  132
#define PXF   132   // packed fragment stride (words)

// SMEM word offsets
#define ATT_OFF 33792              // after packed X: 4*64 frags * 132
#define STG_OFF (ATT_OFF + 4224)   // 16384-word weight staging zone (4 x 4096)
#define FG_OFF  STG_OFF            // FG (64x132) lives in staging zone head; dead before staging starts
#define RS_OFF  (STG_OFF + 16384)
#define ST_OFF  (RS_OFF + 64)
#define BAR_OFF (ST_OFF + 128)     // 16 mbarriers * 2 words
#define SM_TOT  (BAR_OFF + 32)     // 54624 words = 218496 B

__device__ float g_inv_sigma;
__device__ __align__(16) float g_whP [262144];
__device__ __align__(16) float g_wsnP[262144];
__device__ __align__(16) float g_fgP [65536];

__device__ __forceinline__ unsigned f2tf(float f) {
    unsigned r;
    asm("cvt.rna.tf32.f32 %0, %1;" : "=r"(r) : "f"(f));
    return r;
}
__device__ __forceinline__ float rndtf(float f) { return __uint_as_float(f2tf(f)); }
__device__ __forceinline__ unsigned bits(float f) { return __float_as_uint(f); }

__device__ __forceinline__ void mma_tf32(float* c,
                                         unsigned a0, unsigned a1, unsigned a2, unsigned a3,
                                         unsigned b0, unsigned b1) {
    asm volatile(
        "mma.sync.aligned.m16n8k8.row.col.f32.tf32.tf32.f32 "
        "{%0,%1,%2,%3}, {%4,%5,%6,%7}, {%8,%9}, {%0,%1,%2,%3};\n"
        : "+f"(c[0]), "+f"(c[1]), "+f"(c[2]), "+f"(c[3])
        : "r"(a0), "r"(a1), "r"(a2), "r"(a3), "r"(b0), "r"(b1));
}

// ---- mbarrier / bulk-copy helpers ----------------------------------------
__device__ __forceinline__ void mbar_init(unsigned a, unsigned cnt) {
    asm volatile("mbarrier.init.shared.b64 [%0], %1;" :: "r"(a), "r"(cnt) : "memory");
}
__device__ __forceinline__ void mbar_arrive(unsigned a) {
    asm volatile("mbarrier.arrive.shared.b64 _, [%0];" :: "r"(a) : "memory");
}
__device__ __forceinline__ void mbar_wait(unsigned a, unsigned parity) {
    unsigned done = 0;
    while (!done) {
        asm volatile(
            "{\n\t.reg .pred p;\n\t"
            "mbarrier.try_wait.parity.acquire.cta.shared::cta.b64 p, [%1], %2, 0x989680;\n\t"
            "selp.b32 %0, 1, 0, p;\n\t}"
            : "=r"(done) : "r"(a), "r"(parity) : "memory");
    }
}
// 16KB gmem->smem bulk copy with transaction-count completion on fullb.
__device__ __forceinline__ void issue_stage(unsigned dst_s, const float* src, unsigned fullb) {
    asm volatile("mbarrier.arrive.expect_tx.shared.b64 _, [%0], %1;"
                 :: "r"(fullb), "r"(16384u) : "memory");
    asm volatile("cp.async.bulk.shared::cluster.global.mbarrier::complete_tx::bytes "
                 "[%0], [%1], %2, [%3];"
                 :: "r"(dst_s), "l"(src), "r"(16384u), "r"(fullb) : "memory");
}

// ---------------------------------------------------------------------------
__global__ __launch_bounds__(512)
void init_kernel(const float* __restrict__ wf, const float* __restrict__ wg,
                 const float* __restrict__ wh, const float* __restrict__ wsn,
                 const float* __restrict__ usn) {
    if (blockIdx.x < 512) {
        int i = blockIdx.x * 512 + threadIdx.x;
        {
            int j = i & 3, l = (i >> 2) & 31, h = (i >> 7) & 1, r = (i >> 8) & 1;
            int ng = (i >> 9) & 7, ks = i >> 12;
            int row = ks * 8 + (l & 3) + r * 4;
            int col = ng * 64 + (h * 4 + j) * 8 + (l >> 2);
            g_whP[i]  = rndtf(wh [(size_t)row * SDIM + col]);
            g_wsnP[i] = rndtf(wsn[(size_t)row * SDIM + col]);
        }
        if (i < 65536) {
            int j = i & 3, l = (i >> 2) & 31, r = (i >> 7) & 1;
            int ng = (i >> 8) & 3, ks = i >> 10;
            int row = ks * 8 + (l & 3) + r * 4;
            int col = ng * 32 + j * 8 + (l >> 2);
            g_fgP[i] = rndtf(col < 64 ? wf[(size_t)row * C8 + col]
                                      : wg[(size_t)row * C8 + col - 64]);
        }
        return;
    }
    __shared__ float us[512];
    __shared__ float vs[512];
    __shared__ float red[17];
    int tid = threadIdx.x, wid = tid >> 5, lane = tid & 31;
    us[tid] = usn[tid];
    __syncthreads();

    float q = 0.f;
    for (int rr = 0; rr < 32; rr++) {
        int row = wid * 32 + rr;
        const float4* wr = (const float4*)(wsn + (size_t)row * SDIM);
        const float4* ur = (const float4*)us;
        float s = 0.f;
        #pragma unroll
        for (int i = 0; i < 4; i++) {
            float4 w = wr[lane + i * 32], u = ur[lane + i * 32];
            s += w.x * u.x + w.y * u.y + w.z * u.z + w.w * u.w;
        }
        #pragma unroll
        for (int o = 16; o; o >>= 1) s += __shfl_xor_sync(0xffffffffu, s, o);
        if (lane == 0) { vs[row] = s; q += s * s; }
    }
    if (lane == 0) red[wid] = q;
    __syncthreads();
    if (tid == 0) {
        float z = 0.f;
        for (int i = 0; i < 16; i++) z += red[i];
        red[16] = 1.f / (sqrtf(z) + 1e-12f);
    }
    __syncthreads();
    float inv_nv = red[16];
    __syncthreads();

    float t0 = 0.f, t1 = 0.f, t2 = 0.f, t3 = 0.f;
    for (int i = 0; i < SDIM; i += 4) {
        t0 += vs[i + 0] * wsn[(size_t)(i + 0) * SDIM + tid];
        t1 += vs[i + 1] * wsn[(size_t)(i + 1) * SDIM + tid];
        t2 += vs[i + 2] * wsn[(size_t)(i + 2) * SDIM + tid];
        t3 += vs[i + 3] * wsn[(size_t)(i + 3) * SDIM + tid];
    }
    float tj = ((t0 + t1) + (t2 + t3)) * inv_nv;
    float q2 = tj * tj;
    #pragma unroll
    for (int o = 16; o; o >>= 1) q2 += __shfl_xor_sync(0xffffffffu, q2, o);
    if (lane == 0) red[wid] = q2;
    __syncthreads();
    if (tid == 0) {
        float z = 0.f;
        for (int i = 0; i < 16; i++) z += red[i];
        float nt = sqrtf(z);
        g_inv_sigma = (nt + 1e-12f) / z;
    }
}

// ---------------------------------------------------------------------------
extern __shared__ float smf[];

__global__ __launch_bounds__(512, 1)
void fused_kernel(const float* __restrict__ x,
                  const float* __restrict__ bf, const float* __restrict__ bg,
                  const float* __restrict__ bh,
                  const float* __restrict__ gamma,
                  const float* __restrict__ ln1g, const float* __restrict__ ln1b,
                  const float* __restrict__ ln2g, const float* __restrict__ ln2b,
                  float* __restrict__ out) {
    float* Xs     = smf;             // packed X -> packed AX -> row-major out1
    float* ATTp   = smf + ATT_OFF;   // packed ATT (32 frags)
    float* FGs    = smf + FG_OFF;    // 64x132 row-major (dies before staging starts)
    float* STG    = smf + STG_OFF;   // 4 x 4096-word weight stages
    float* rowsum = smf + RS_OFF;
    float* stats  = smf + ST_OFF;

    const int tid  = threadIdx.x;
    const int wid  = tid >> 5;
    const int lane = tid & 31;
    const int g    = lane >> 2;
    const int t    = lane & 3;
    const size_t base = (size_t)blockIdx.x * (WDIM * SDIM);

    const unsigned barb = (unsigned)__cvta_generic_to_shared(smf + BAR_OFF);
    const unsigned full4  = barb;        // 4 x 8B
    const unsigned empty4 = barb + 32;
    const unsigned full5  = barb + 64;
    const unsigned empty5 = barb + 96;
    const unsigned stg_s  = (unsigned)__cvta_generic_to_shared(STG);

    if (tid == 0) {
        #pragma unroll
        for (int s = 0; s < 4; s++) {
            mbar_init(full4  + s * 8, 1);
            mbar_init(empty4 + s * 8, 16);
            mbar_init(full5  + s * 8, 1);
            mbar_init(empty5 + s * 8, 16);
        }
    }

    // ---- load X -> packed fragment layout, pre-rounded ----
    for (int i = tid; i < WDIM * SDIM / 4; i += 512) {
        float4 v = ((const float4*)(x + base))[i];
        int r = i >> 7;
        int c = (i & 127) << 2;
        int b = ((r >> 4) * 64 + (c >> 3)) * PXF + (r & 7) * 16
              + ((r >> 3) & 1) + 2 * ((c >> 2) & 1);
        Xs[b]      = rndtf(v.x);
        Xs[b + 4]  = rndtf(v.y);
        Xs[b + 8]  = rndtf(v.z);
        Xs[b + 12] = rndtf(v.w);
    }
    __syncthreads();   // X + mbarrier init visible

    // ---- GEMM1: [F|G] = X @ [Wf|Wg] + bias  (direct LDG weights, frag A) ----
    {
        const int mg1 = wid & 3;
        const int ng1 = wid >> 2;
        const float4* Af1 = (const float4*)Xs + (size_t)mg1 * 64 * 33 + lane;
        const uint4* fgp = (const uint4*)g_fgP + (size_t)(ng1 * 2) * 32 + lane;
        float acc1[4][4];
        #pragma unroll
        for (int nj = 0; nj < 4; nj++)
            #pragma unroll
            for (int c = 0; c < 4; c++) acc1[nj][c] = 0.f;

        #pragma unroll 2
        for (int ks = 0; ks < 64; ks++) {
            const uint4* p = fgp + (size_t)ks * 256;
            uint4 B0 = p[0];
            uint4 B1 = p[32];
            unsigned b0[4] = {B0.x, B0.y, B0.z, B0.w};
            unsigned b1[4] = {B1.x, B1.y, B1.z, B1.w};
            float4 av = Af1[(size_t)ks * 33];
            unsigned a0 = bits(av.x), a1 = bits(av.y), a2 = bits(av.z), a3 = bits(av.w);
            #pragma unroll
            for (int nj = 0; nj < 4; nj++)
                mma_tf32(acc1[nj], a0, a1, a2, a3, b0[nj], b1[nj]);
        }
        const int rA = mg1 * 16 + g;
        #pragma unroll
        for (int nj = 0; nj < 4; nj++) {
            int cg = ng1 * 32 + nj * 8 + 2 * t;
            float bias0 = (cg < 64) ? bf[cg] : bg[cg - 64];
            float bias1 = (cg + 1 < 64) ? bf[cg + 1] : bg[cg + 1 - 64];
            FGs[rA * FGST + cg]           = rndtf(acc1[nj][0] + bias0);
            FGs[rA * FGST + cg + 1]       = rndtf(acc1[nj][1] + bias1);
            FGs[(rA + 8) * FGST + cg]     = rndtf(acc1[nj][2] + bias0);
            FGs[(rA + 8) * FGST + cg + 1] = rndtf(acc1[nj][3] + bias1);
        }
    }
    __syncthreads();

    const int mhalf = wid >> 3;
    const int n8    = (wid & 7) * 8;
    const int fb8   = n8 >> 3;

    // ---- GEMM2: ATT = sigmoid(F @ G^T) -> packed ATTp ----
    {
        float acc2[2][4];
        #pragma unroll
        for (int mi = 0; mi < 2; mi++)
            #pragma unroll
            for (int c = 0; c < 4; c++) acc2[mi][c] = 0.f;

        #pragma unroll
        for (int k = 0; k < 64; k += 8) {
            unsigned b0 = bits(FGs[(n8 + g) * FGST + 64 + k + t]);
            unsigned b1 = bits(FGs[(n8 + g) * FGST + 64 + k + t + 4]);
            #pragma unroll
            for (int mi = 0; mi < 2; mi++) {
                int r = (mhalf * 2 + mi) * 16 + g;
                unsigned a0 = bits(FGs[r * FGST + k + t]);
                unsigned a1 = bits(FGs[(r + 8) * FGST + k + t]);
                unsigned a2 = bits(FGs[r * FGST + k + t + 4]);
                unsigned a3 = bits(FGs[(r + 8) * FGST + k + t + 4]);
                mma_tf32(acc2[mi], a0, a1, a2, a3, b0, b1);
            }
        }
        #pragma unroll
        for (int mi = 0; mi < 2; mi++) {
            int f = (mhalf * 2 + mi) * 8 + fb8;
            int w0 = f * PXF + (g * 4 + 2 * (t & 1)) * 4 + 2 * (t >> 1);
            ATTp[w0]     = rndtf(1.f / (1.f + __expf(-acc2[mi][0])));
            ATTp[w0 + 4] = rndtf(1.f / (1.f + __expf(-acc2[mi][1])));
            ATTp[w0 + 1] = rndtf(1.f / (1.f + __expf(-acc2[mi][2])));
            ATTp[w0 + 5] = rndtf(1.f / (1.f + __expf(-acc2[mi][3])));
        }
    }
    __syncthreads();     // FG dead from here -> staging zone free

    // GEMM4 staging prologue: 4 stages of Wh land while GEMM3 computes.
    if (tid == 0) {
        #pragma unroll
        for (int j = 0; j < 4; j++)
            issue_stage(stg_s + j * 16384u, g_whP + (size_t)j * 4096, full4 + j * 8);
    }

    if (tid < 64) {
        int R = tid;
        int inner = (R & 7) * 16 + ((R >> 3) & 1);
        int frb = (R >> 4) * 8;
        float s = 0.f;
        for (int v = 0; v < 64; v++) {
            int w = (frb + (v >> 3)) * PXF + inner + (v & 3) * 4 + 2 * ((v >> 2) & 1);
            s += ATTp[w];
        }
        rowsum[R] = s;
    }

    // ---- GEMM3: AX = ATT @ X, chunk-by-chunk, overwriting X in place ----
    for (int kc = 0; kc < 8; kc++) {
        const int C3 = kc * 8 + fb8;

        float axc[2][4];
        #pragma unroll
        for (int mi = 0; mi < 2; mi++)
            #pragma unroll
            for (int c = 0; c < 4; c++) axc[mi][c] = 0.f;

        #pragma unroll
        for (int ks = 0; ks < 8; ks++) {
            int k = ks * 8;
            int wb0 = ((k >> 4) * 64 + C3) * PXF + t * 16 + (g & 3) * 4
                    + ((k >> 3) & 1) + 2 * ((g >> 2) & 1);
            unsigned b0 = bits(Xs[wb0]);
            unsigned b1 = bits(Xs[wb0 + 64]);
            #pragma unroll
            for (int mi = 0; mi < 2; mi++) {
                float4 av = ((const float4*)ATTp)[(size_t)((mhalf * 2 + mi) * 8 + ks) * 33 + lane];
                mma_tf32(axc[mi], bits(av.x), bits(av.y), bits(av.z), bits(av.w), b0, b1);
            }
        }
        __syncthreads();   // all reads of X chunk kc complete
        #pragma unroll
        for (int mi = 0; mi < 2; mi++) {
            int f = ((mhalf * 2 + mi) * 64) + C3;      // full-width packed AX
            int w0 = f * PXF + (g * 4 + 2 * (t & 1)) * 4 + 2 * (t >> 1);
            Xs[w0]     = rndtf(axc[mi][0]);
            Xs[w0 + 4] = rndtf(axc[mi][1]);
            Xs[w0 + 1] = rndtf(axc[mi][2]);
            Xs[w0 + 5] = rndtf(axc[mi][3]);
        }
    }
    __syncthreads();       // full packed AX visible to all warps

    // ---- GEMM4: ATTN = AX @ Wh  (streaming, mbarrier-staged weights) ----
    const int mg = wid & 1;
    const int ng = wid >> 1;

    float acc[2][8][4];
    #pragma unroll
    for (int mi = 0; mi < 2; mi++)
        #pragma unroll
        for (int nj = 0; nj < 8; nj++)
            #pragma unroll
            for (int c = 0; c < 4; c++) acc[mi][nj][c] = 0.f;

    for (int i = 0; i < 64; i++) {
        const int slot = i & 3;
        const unsigned par = (unsigned)((i >> 2) & 1);
        mbar_wait(full4 + slot * 8, par);
        const uint4* p = (const uint4*)(STG + slot * 4096) + ng * 128 + lane;
        uint4 Bv0 = p[0];
        uint4 Bv1 = p[32];
        uint4 Bv2 = p[64];
        uint4 Bv3 = p[96];
        unsigned b0[8] = {Bv0.x, Bv0.y, Bv0.z, Bv0.w, Bv1.x, Bv1.y, Bv1.z, Bv1.w};
        unsigned b1[8] = {Bv2.x, Bv2.y, Bv2.z, Bv2.w, Bv3.x, Bv3.y, Bv3.z, Bv3.w};
        #pragma unroll
        for (int mi = 0; mi < 2; mi++) {
            float4 av = ((const float4*)Xs)[(size_t)((mg * 2 + mi) * 64 + i) * 33 + lane];
            unsigned a0 = bits(av.x), a1 = bits(av.y), a2 = bits(av.z), a3 = bits(av.w);
            #pragma unroll
            for (int nj = 0; nj < 8; nj++)
                mma_tf32(acc[mi][nj], a0, a1, a2, a3, b0[nj], b1[nj]);
        }
        if (lane == 0) mbar_arrive(empty4 + slot * 8);
        if (tid == 0 && i < 60) {
            mbar_wait(empty4 + slot * 8, par);
            issue_stage(stg_s + slot * 16384u, g_whP + (size_t)(i + 4) * 4096, full4 + slot * 8);
        }
    }
    __syncthreads();       // all stage reads + AX reads done

    // GEMM5 staging prologue: Wsn stages land while epilogue1 + LN1 run.
    if (tid == 0) {
        #pragma unroll
        for (int j = 0; j < 4; j++)
            issue_stage(stg_s + j * 16384u, g_wsnP + (size_t)j * 4096, full5 + j * 8);
    }

    // ---- epilogue 1: Xs (row-major now) = gamma*(attn + rowsum*bh) ----
    {
        float gam = gamma[0];
        #pragma unroll
        for (int mi = 0; mi < 2; mi++) {
            int r0 = mg * 32 + mi * 16 + g, r1 = r0 + 8;
            float rs0 = rowsum[r0], rs1 = rowsum[r1];
            #pragma unroll
            for (int nj = 0; nj < 8; nj++) {
                int c0 = ng * 64 + nj * 8 + 2 * t;
                float bh0 = bh[c0], bh1 = bh[c0 + 1];
                Xs[r0 * ROWST + c0]     = gam * (acc[mi][nj][0] + rs0 * bh0);
                Xs[r0 * ROWST + c0 + 1] = gam * (acc[mi][nj][1] + rs0 * bh1);
                Xs[r1 * ROWST + c0]     = gam * (acc[mi][nj][2] + rs1 * bh0);
                Xs[r1 * ROWST + c0 + 1] = gam * (acc[mi][nj][3] + rs1 * bh1);
            }
        }
    }
    __syncthreads();

    // ---- LN1 pass1: add residual x (re-read), stats ----
    {
        int row = tid >> 3, j0 = tid & 7;
        const float4* xr = (const float4*)(x + base + (size_t)row * SDIM);
        float4* Xr = (float4*)(Xs + row * ROWST);
        float s = 0.f, sq = 0.f;
        #pragma unroll
        for (int i = 0; i < 16; i++) {
            int c4 = j0 + i * 8;
            float4 v = Xr[c4];
            float4 xv = xr[c4];
            v.x += xv.x; v.y += xv.y; v.z += xv.z; v.w += xv.w;
            Xr[c4] = v;
            s  += (v.x + v.y) + (v.z + v.w);
            sq += (v.x * v.x + v.y * v.y) + (v.z * v.z + v.w * v.w);
        }
        #pragma unroll
        for (int o = 1; o <= 4; o <<= 1) {
            s  += __shfl_xor_sync(0xffffffffu, s, o);
            sq += __shfl_xor_sync(0xffffffffu, sq, o);
        }
        if (j0 == 0) {
            float mean = s * (1.f / SDIM);
            float var  = sq * (1.f / SDIM) - mean * mean;
            stats[row * 2]     = mean;
            stats[row * 2 + 1] = rsqrtf(var + 1e-6f);
        }
    }
    __syncthreads();
    // ---- LN1 pass2: normalize, pre-round ----
    {
        int row = tid >> 3, j0 = tid & 7;
        float mean = stats[row * 2], rstd = stats[row * 2 + 1];
        float4* Xr = (float4*)(Xs + row * ROWST);
        #pragma unroll
        for (int i = 0; i < 16; i++) {
            int c4 = j0 + i * 8;
            float4 v = Xr[c4];
            float4 gv = ((const float4*)ln1g)[c4];
            float4 bv = ((const float4*)ln1b)[c4];
            v.x = rndtf((v.x - mean) * rstd * gv.x + bv.x);
            v.y = rndtf((v.y - mean) * rstd * gv.y + bv.y);
            v.z = rndtf((v.z - mean) * rstd * gv.z + bv.z);
            v.w = rndtf((v.w - mean) * rstd * gv.w + bv.w);
            Xr[c4] = v;
        }
    }
    __syncthreads();       // out1 visible to all warps

    // ---- GEMM5: Y = out1 @ Wsn  (streaming, mbarrier-staged weights) ----
    #pragma unroll
    for (int mi = 0; mi < 2; mi++)
        #pragma unroll
        for (int nj = 0; nj < 8; nj++)
            #pragma unroll
            for (int c = 0; c < 4; c++) acc[mi][nj][c] = 0.f;

    for (int i = 0; i < 64; i++) {
        const int slot = i & 3;
        const unsigned par = (unsigned)((i >> 2) & 1);
        mbar_wait(full5 + slot * 8, par);
        const uint4* p = (const uint4*)(STG + slot * 4096) + ng * 128 + lane;
        uint4 Bv0 = p[0];
        uint4 Bv1 = p[32];
        uint4 Bv2 = p[64];
        uint4 Bv3 = p[96];
        unsigned b0[8] = {Bv0.x, Bv0.y, Bv0.z, Bv0.w, Bv1.x, Bv1.y, Bv1.z, Bv1.w};
        unsigned b1[8] = {Bv2.x, Bv2.y, Bv2.z, Bv2.w, Bv3.x, Bv3.y, Bv3.z, Bv3.w};
        int k = i * 8;
        #pragma unroll
        for (int mi = 0; mi < 2; mi++) {
            int r = mg * 32 + mi * 16 + g;
            unsigned a0 = bits(Xs[r * ROWST + k + t]);
            unsigned a1 = bits(Xs[(r + 8) * ROWST + k + t]);
            unsigned a2 = bits(Xs[r * ROWST + k + t + 4]);
            unsigned a3 = bits(Xs[(r + 8) * ROWST + k + t + 4]);
            #pragma unroll
            for (int nj = 0; nj < 8; nj++)
                mma_tf32(acc[mi][nj], a0, a1, a2, a3, b0[nj], b1[nj]);
        }
        if (lane == 0) mbar_arrive(empty5 + slot * 8);
        if (tid == 0 && i < 60) {
            mbar_wait(empty5 + slot * 8, par);
            issue_stage(stg_s + slot * 16384u, g_wsnP + (size_t)(i + 4) * 4096, full5 + slot * 8);
        }
    }
    __syncthreads();       // all warps done reading out1 before overwrite

    // ---- epilogue 2: relu(acc/sigma) -> Xs ----
    {
        float invsig = g_inv_sigma;
        #pragma unroll
        for (int mi = 0; mi < 2; mi++) {
            int r0 = mg * 32 + mi * 16 + g, r1 = r0 + 8;
            #pragma unroll
            for (int nj = 0; nj < 8; nj++) {
                int c0 = ng * 64 + nj * 8 + 2 * t;
                Xs[r0 * ROWST + c0]     = fmaxf(acc[mi][nj][0] * invsig, 0.f);
                Xs[r0 * ROWST + c0 + 1] = fmaxf(acc[mi][nj][1] * invsig, 0.f);
                Xs[r1 * ROWST + c0]     = fmaxf(acc[mi][nj][2] * invsig, 0.f);
                Xs[r1 * ROWST + c0 + 1] = fmaxf(acc[mi][nj][3] * invsig, 0.f);
            }
        }
    }
    __syncthreads();

    // ---- LN2 pass1 ----
    {
        int row = tid >> 3, j0 = tid & 7;
        const float4* Xr = (const float4*)(Xs + row * ROWST);
        float s = 0.f, sq = 0.f;
        #pragma unroll
        for (int i = 0; i < 16; i++) {
            float4 v = Xr[j0 + i * 8];
            s  += (v.x + v.y) + (v.z + v.w);
            sq += (v.x * v.x + v.y * v.y) + (v.z * v.z + v.w * v.w);
        }
        #pragma unroll
        for (int o = 1; o <= 4; o <<= 1) {
            s  += __shfl_xor_sync(0xffffffffu, s, o);
            sq += __shfl_xor_sync(0xffffffffu, sq, o);
        }
        if (j0 == 0) {
            float mean = s * (1.f / SDIM);
            float var  = sq * (1.f / SDIM) - mean * mean;
            stats[row * 2]     = mean;
            stats[row * 2 + 1] = rsqrtf(var + 1e-6f);
        }
    }
    __syncthreads();
    // ---- LN2 pass2 -> global out ----
    {
        int row = tid >> 3, j0 = tid & 7;
        float mean = stats[row * 2], rstd = stats[row * 2 + 1];
        const float4* Xr = (const float4*)(Xs + row * ROWST);
        float4* orow = (float4*)(out + base + (size_t)row * SDIM);
        #pragma unroll
        for (int i = 0; i < 16; i++) {
            int c4 = j0 + i * 8;
            float4 v = Xr[c4];
            float4 gv = ((const float4*)ln2g)[c4];
            float4 bv = ((const float4*)ln2b)[c4];
            v.x = (v.x - mean) * rstd * gv.x + bv.x;
            v.y = (v.y - mean) * rstd * gv.y + bv.y;
            v.z = (v.z - mean) * rstd * gv.z + bv.z;
            v.w = (v.w - mean) * rstd * gv.w + bv.w;
            orow[c4] = v;
        }
    }
}

// ---------------------------------------------------------------------------
extern "C" void kernel_launch(void* const* d_in, const int* in_sizes, int n_in,
                              void* d_out, int out_size) {
    (void)in_sizes; (void)n_in; (void)out_size;
    const float* x    = (const float*)d_in[0];
    const float* wf   = (const float*)d_in[1];
    const float* bf   = (const float*)d_in[2];
    const float* wg   = (const float*)d_in[3];
    const float* bg   = (const float*)d_in[4];
    const float* wh   = (const float*)d_in[5];
    const float* bh   = (const float*)d_in[6];
    const float* gam  = (const float*)d_in[7];
    const float* ln1g = (const float*)d_in[8];
    const float* ln1b = (const float*)d_in[9];
    const float* wsn  = (const float*)d_in[10];
    const float* usn  = (const float*)d_in[11];
    const float* ln2g = (const float*)d_in[12];
    const float* ln2b = (const float*)d_in[13];
    float* out = (float*)d_out;

    init_kernel<<<513, 512>>>(wf, wg, wh, wsn, usn);

    const int smem_bytes = SM_TOT * 4;
    cudaFuncSetAttribute(fused_kernel, cudaFuncAttributeMaxDynamicSharedMemorySize, smem_bytes);
    fused_kernel<<<1024, 512, smem_bytes>>>(x, bf, bg, bh, gam,
                                            ln1g, ln1b, ln2g, ln2b, out);
}

// round 13
// speedup vs baseline: 1.7752x; 1.7752x over previous
#include <cuda_runtime.h>
#include <cuda_fp16.h>

#define SDIM 512

// SMEM layout (half-element offsets unless noted)
#define XRM_H 0            // 64 x 520 halves  (X row-major -> AX)
#define XT_H  33280        // 512 x 72 halves  (X transposed -> out1h)
#define FG_H  70144        // 64 x 136 halves
#define ATT_H 78848        // 64 x 72 halves
// float offsets (in floats from smem base)
#define SP_F  41728        // stats partials: (ng*64+row)*2, 1024 floats
#define RS_F  42752        // rowsum 64
#define ST_F  42816        // stats 128
#define SM_BYTES (42944 * 4)

__device__ float g_inv_sigma;
__device__ __align__(16) __half g_whH [262144];
__device__ __align__(16) __half g_wsnH[262144];
__device__ __align__(16) __half g_fgH [65536];

__device__ __forceinline__ void mma16(float* c,
                                      unsigned a0, unsigned a1, unsigned a2, unsigned a3,
                                      unsigned b0, unsigned b1) {
    asm volatile(
        "mma.sync.aligned.m16n8k16.row.col.f32.f16.f16.f32 "
        "{%0,%1,%2,%3}, {%4,%5,%6,%7}, {%8,%9}, {%0,%1,%2,%3};\n"
        : "+f"(c[0]), "+f"(c[1]), "+f"(c[2]), "+f"(c[3])
        : "r"(a0), "r"(a1), "r"(a2), "r"(a3), "r"(b0), "r"(b1));
}

// ---------------------------------------------------------------------------
// init: blocks 0..511 pack fp16 weights (fragment order); block 512 = sigma.
// whH/wsnH half linear idx: ks*8192 + ng*1024 + s*256 + lane*8 + j*2 + j2
// fgH:                      ks*2048 + ng*512  + r*256 + lane*8 + j*2 + j2
// ---------------------------------------------------------------------------
__global__ __launch_bounds__(512)
void init_kernel(const float* __restrict__ wf, const float* __restrict__ wg,
                 const float* __restrict__ wh, const float* __restrict__ wsn,
                 const float* __restrict__ usn) {
    if (blockIdx.x < 512) {
        int i = blockIdx.x * 512 + threadIdx.x;        // 0..262143
        {
            int j2 = i & 1, j = (i >> 1) & 3, lane = (i >> 3) & 31;
            int s = (i >> 8) & 3, ng = (i >> 10) & 7, ks = i >> 13;
            int r = s >> 1, h = s & 1;
            int col = ng * 64 + (h * 4 + j) * 8 + (lane >> 2);
            int k = ks * 16 + (lane & 3) * 2 + r * 8 + j2;
            g_whH [i] = __float2half_rn(wh [(size_t)k * SDIM + col]);
            g_wsnH[i] = __float2half_rn(wsn[(size_t)k * SDIM + col]);
        }
        if (i < 65536) {
            int j2 = i & 1, j = (i >> 1) & 3, lane = (i >> 3) & 31;
            int r = (i >> 8) & 1, ng = (i >> 9) & 3, ks = i >> 11;
            int col = ng * 32 + j * 8 + (lane >> 2);
            int k = ks * 16 + (lane & 3) * 2 + r * 8 + j2;
            g_fgH[i] = __float2half_rn(col < 64 ? wf[(size_t)k * 64 + col]
                                                : wg[(size_t)k * 64 + col - 64]);
        }
        return;
    }
    // ---- sigma ----
    __shared__ float us[512];
    __shared__ float vs[512];
    __shared__ float red[17];
    int tid = threadIdx.x, wid = tid >> 5, lane = tid & 31;
    us[tid] = usn[tid];
    __syncthreads();

    float q = 0.f;
    for (int rr = 0; rr < 32; rr++) {
        int row = wid * 32 + rr;
        const float4* wr = (const float4*)(wsn + (size_t)row * SDIM);
        const float4* ur = (const float4*)us;
        float s = 0.f;
        #pragma unroll
        for (int i = 0; i < 4; i++) {
            float4 w = wr[lane + i * 32], u = ur[lane + i * 32];
            s += w.x * u.x + w.y * u.y + w.z * u.z + w.w * u.w;
        }
        #pragma unroll
        for (int o = 16; o; o >>= 1) s += __shfl_xor_sync(0xffffffffu, s, o);
        if (lane == 0) { vs[row] = s; q += s * s; }
    }
    if (lane == 0) red[wid] = q;
    __syncthreads();
    if (tid == 0) {
        float z = 0.f;
        for (int i = 0; i < 16; i++) z += red[i];
        red[16] = 1.f / (sqrtf(z) + 1e-12f);
    }
    __syncthreads();
    float inv_nv = red[16];
    __syncthreads();

    float t0 = 0.f, t1 = 0.f, t2 = 0.f, t3 = 0.f;
    for (int i = 0; i < SDIM; i += 4) {
        t0 += vs[i + 0] * wsn[(size_t)(i + 0) * SDIM + tid];
        t1 += vs[i + 1] * wsn[(size_t)(i + 1) * SDIM + tid];
        t2 += vs[i + 2] * wsn[(size_t)(i + 2) * SDIM + tid];
        t3 += vs[i + 3] * wsn[(size_t)(i + 3) * SDIM + tid];
    }
    float tj = ((t0 + t1) + (t2 + t3)) * inv_nv;
    float q2 = tj * tj;
    #pragma unroll
    for (int o = 16; o; o >>= 1) q2 += __shfl_xor_sync(0xffffffffu, q2, o);
    if (lane == 0) red[wid] = q2;
    __syncthreads();
    if (tid == 0) {
        float z = 0.f;
        for (int i = 0; i < 16; i++) z += red[i];
        float nt = sqrtf(z);
        g_inv_sigma = (nt + 1e-12f) / z;
    }
}

// ---------------------------------------------------------------------------
// Streaming fp16 GEMM mainloop: acc[2][8][4] += A(64x512 row-major halves,
// stride 260 words) @ Wpacked. 32 ksteps of 16.
// ---------------------------------------------------------------------------
__device__ __forceinline__ void gemm_half(float (&acc)[2][8][4],
                                          const unsigned* __restrict__ Au,
                                          const __half* __restrict__ WH,
                                          int mg, int ng, int g, int t) {
    const uint4* wp = (const uint4*)WH + (size_t)ng * 128 + (unsigned)(g * 4 + t);
    #pragma unroll 2
    for (int ks = 0; ks < 32; ks++) {
        const uint4* p = wp + (size_t)ks * 1024;
        uint4 Bv0 = p[0];
        uint4 Bv1 = p[32];
        uint4 Bv2 = p[64];
        uint4 Bv3 = p[96];
        unsigned b0[8] = {Bv0.x, Bv0.y, Bv0.z, Bv0.w, Bv1.x, Bv1.y, Bv1.z, Bv1.w};
        unsigned b1[8] = {Bv2.x, Bv2.y, Bv2.z, Bv2.w, Bv3.x, Bv3.y, Bv3.z, Bv3.w};
        int kw = ks * 8;
        #pragma unroll
        for (int mi = 0; mi < 2; mi++) {
            int r = mg * 32 + mi * 16 + g;
            unsigned a0 = Au[r * 260 + kw + t];
            unsigned a1 = Au[(r + 8) * 260 + kw + t];
            unsigned a2 = Au[r * 260 + kw + 4 + t];
            unsigned a3 = Au[(r + 8) * 260 + kw + 4 + t];
            #pragma unroll
            for (int nj = 0; nj < 8; nj++)
                mma16(acc[mi][nj], a0, a1, a2, a3, b0[nj], b1[nj]);
        }
    }
}

// ---------------------------------------------------------------------------
extern __shared__ char smch[];

__global__ __launch_bounds__(512, 1)
void fused_kernel(const float* __restrict__ x,
                  const float* __restrict__ bf, const float* __restrict__ bg,
                  const float* __restrict__ bh,
                  const float* __restrict__ gamma,
                  const float* __restrict__ ln1g, const float* __restrict__ ln1b,
                  const float* __restrict__ ln2g, const float* __restrict__ ln2b,
                  float* __restrict__ out) {
    __half* Xrm  = (__half*)smch;            // X row-major -> AX
    __half* Xt   = (__half*)smch + XT_H;     // X transposed -> out1h
    __half* FGh  = (__half*)smch + FG_H;
    __half* ATTh = (__half*)smch + ATT_H;
    float* sp     = (float*)smch + SP_F;
    float* rowsum = (float*)smch + RS_F;
    float* stats  = (float*)smch + ST_F;

    const unsigned* Xu   = (const unsigned*)Xrm;
    const unsigned* Xtu  = (const unsigned*)Xt;
    const unsigned* FGu  = (const unsigned*)FGh;
    const unsigned* ATTu = (const unsigned*)ATTh;

    const int tid  = threadIdx.x;
    const int wid  = tid >> 5;
    const int lane = tid & 31;
    const int g    = lane >> 2;
    const int t    = lane & 3;
    const size_t base = (size_t)blockIdx.x * (64 * SDIM);

    // ---- load X: row-major half + transposed half ----
    for (int i = tid; i < 8192; i += 512) {
        float4 v = ((const float4*)(x + base))[i];
        int r = i >> 7;
        int c = (i & 127) << 2;
        __half h0 = __float2half_rn(v.x), h1 = __float2half_rn(v.y);
        __half h2 = __float2half_rn(v.z), h3 = __float2half_rn(v.w);
        __half2* w2 = (__half2*)Xrm + r * 260 + (c >> 1);
        w2[0] = __halves2half2(h0, h1);
        w2[1] = __halves2half2(h2, h3);
        Xt[(c + 0) * 72 + r] = h0;
        Xt[(c + 1) * 72 + r] = h1;
        Xt[(c + 2) * 72 + r] = h2;
        Xt[(c + 3) * 72 + r] = h3;
    }
    __syncthreads();

    // ---- GEMM1: [F|G] = X @ [Wf|Wg] + bias ----
    {
        const int mg1 = wid & 3;
        const int ng1 = wid >> 2;
        const uint4* fgp = (const uint4*)g_fgH + (size_t)ng1 * 64 + lane;
        float acc1[4][4];
        #pragma unroll
        for (int nj = 0; nj < 4; nj++)
            #pragma unroll
            for (int c = 0; c < 4; c++) acc1[nj][c] = 0.f;

        const int rA = mg1 * 16 + g;
        #pragma unroll 2
        for (int ks = 0; ks < 32; ks++) {
            const uint4* p = fgp + (size_t)ks * 256;
            uint4 B0 = p[0];
            uint4 B1 = p[32];
            unsigned b0[4] = {B0.x, B0.y, B0.z, B0.w};
            unsigned b1[4] = {B1.x, B1.y, B1.z, B1.w};
            int kw = ks * 8;
            unsigned a0 = Xu[rA * 260 + kw + t];
            unsigned a1 = Xu[(rA + 8) * 260 + kw + t];
            unsigned a2 = Xu[rA * 260 + kw + 4 + t];
            unsigned a3 = Xu[(rA + 8) * 260 + kw + 4 + t];
            #pragma unroll
            for (int nj = 0; nj < 4; nj++)
                mma16(acc1[nj], a0, a1, a2, a3, b0[nj], b1[nj]);
        }
        #pragma unroll
        for (int nj = 0; nj < 4; nj++) {
            int cg = ng1 * 32 + nj * 8 + 2 * t;
            float bias0 = (cg < 64) ? bf[cg] : bg[cg - 64];
            float bias1 = (cg + 1 < 64) ? bf[cg + 1] : bg[cg + 1 - 64];
            ((__half2*)FGh)[rA * 68 + (cg >> 1)] =
                __floats2half2_rn(acc1[nj][0] + bias0, acc1[nj][1] + bias1);
            ((__half2*)FGh)[(rA + 8) * 68 + (cg >> 1)] =
                __floats2half2_rn(acc1[nj][2] + bias0, acc1[nj][3] + bias1);
        }
    }
    __syncthreads();

    const int mhalf = wid >> 3;
    const int n8    = (wid & 7) * 8;

    // ---- GEMM2: ATT = sigmoid(F @ G^T) ----
    {
        float acc2[2][4];
        #pragma unroll
        for (int mi = 0; mi < 2; mi++)
            #pragma unroll
            for (int c = 0; c < 4; c++) acc2[mi][c] = 0.f;

        unsigned gb0[4], gb1[4];
        #pragma unroll
        for (int ks = 0; ks < 4; ks++) {
            gb0[ks] = FGu[(n8 + g) * 68 + 32 + ks * 8 + t];
            gb1[ks] = FGu[(n8 + g) * 68 + 32 + ks * 8 + 4 + t];
        }
        #pragma unroll
        for (int ks = 0; ks < 4; ks++) {
            int kw = ks * 8;
            #pragma unroll
            for (int mi = 0; mi < 2; mi++) {
                int r = (mhalf * 2 + mi) * 16 + g;
                unsigned a0 = FGu[r * 68 + kw + t];
                unsigned a1 = FGu[(r + 8) * 68 + kw + t];
                unsigned a2 = FGu[r * 68 + kw + 4 + t];
                unsigned a3 = FGu[(r + 8) * 68 + kw + 4 + t];
                mma16(acc2[mi], a0, a1, a2, a3, gb0[ks], gb1[ks]);
            }
        }
        #pragma unroll
        for (int mi = 0; mi < 2; mi++) {
            int r = (mhalf * 2 + mi) * 16 + g;
            float s0 = 1.f / (1.f + __expf(-acc2[mi][0]));
            float s1 = 1.f / (1.f + __expf(-acc2[mi][1]));
            float s2 = 1.f / (1.f + __expf(-acc2[mi][2]));
            float s3 = 1.f / (1.f + __expf(-acc2[mi][3]));
            ((__half2*)ATTh)[r * 36 + (n8 >> 1) + t]       = __floats2half2_rn(s0, s1);
            ((__half2*)ATTh)[(r + 8) * 36 + (n8 >> 1) + t] = __floats2half2_rn(s2, s3);
        }
    }
    __syncthreads();

    if (tid < 64) {
        const __half2* ap = (const __half2*)(ATTh + tid * 72);
        float s = 0.f;
        #pragma unroll 8
        for (int v = 0; v < 32; v++) {
            float2 f = __half22float2(ap[v]);
            s += f.x + f.y;
        }
        rowsum[tid] = s;
    }

    // ---- GEMM3: AX = ATT @ X (B from Xt; overwrite Xrm; no inner barriers) ----
    {
        unsigned aA[2][4][4];
        #pragma unroll
        for (int mi = 0; mi < 2; mi++) {
            int r = (mhalf * 2 + mi) * 16 + g;
            #pragma unroll
            for (int ks = 0; ks < 4; ks++) {
                int kw = ks * 8;
                aA[mi][ks][0] = ATTu[r * 36 + kw + t];
                aA[mi][ks][1] = ATTu[(r + 8) * 36 + kw + t];
                aA[mi][ks][2] = ATTu[r * 36 + kw + 4 + t];
                aA[mi][ks][3] = ATTu[(r + 8) * 36 + kw + 4 + t];
            }
        }
        #pragma unroll 2
        for (int cb = 0; cb < 8; cb++) {
            const int col = cb * 64 + n8 + g;
            const unsigned* XtC = Xtu + col * 36;
            float axc[2][4];
            #pragma unroll
            for (int mi = 0; mi < 2; mi++)
                #pragma unroll
                for (int c = 0; c < 4; c++) axc[mi][c] = 0.f;
            #pragma unroll
            for (int ks = 0; ks < 4; ks++) {
                unsigned b0 = XtC[ks * 8 + t];
                unsigned b1 = XtC[ks * 8 + 4 + t];
                #pragma unroll
                for (int mi = 0; mi < 2; mi++)
                    mma16(axc[mi], aA[mi][ks][0], aA[mi][ks][1],
                          aA[mi][ks][2], aA[mi][ks][3], b0, b1);
            }
            #pragma unroll
            for (int mi = 0; mi < 2; mi++) {
                int r = (mhalf * 2 + mi) * 16 + g;
                int wv = cb * 32 + (n8 >> 1) + t;
                ((__half2*)Xrm)[r * 260 + wv]       = __floats2half2_rn(axc[mi][0], axc[mi][1]);
                ((__half2*)Xrm)[(r + 8) * 260 + wv] = __floats2half2_rn(axc[mi][2], axc[mi][3]);
            }
        }
    }
    __syncthreads();

    // ---- GEMM4: ATTN = AX @ Wh ----
    const int mg = wid & 1;
    const int ng = wid >> 1;
    float acc[2][8][4];
    #pragma unroll
    for (int mi = 0; mi < 2; mi++)
        #pragma unroll
        for (int nj = 0; nj < 8; nj++)
            #pragma unroll
            for (int c = 0; c < 4; c++) acc[mi][nj][c] = 0.f;
    gemm_half(acc, Xu, g_whH, mg, ng, g, t);

    // ---- epilogue 1 in registers: v = gamma*(attn + rowsum*bh) + x ----
    {
        float gam = gamma[0];
        #pragma unroll
        for (int mi = 0; mi < 2; mi++) {
            int rA = mg * 32 + mi * 16 + g, rB = rA + 8;
            float rsA = rowsum[rA], rsB = rowsum[rB];
            float sA = 0.f, qA = 0.f, sB = 0.f, qB = 0.f;
            #pragma unroll
            for (int nj = 0; nj < 8; nj++) {
                int c0 = ng * 64 + nj * 8 + 2 * t;
                float2 bhv = *(const float2*)(bh + c0);
                float2 xA = *(const float2*)(x + base + (size_t)rA * SDIM + c0);
                float2 xB = *(const float2*)(x + base + (size_t)rB * SDIM + c0);
                float v0 = gam * (acc[mi][nj][0] + rsA * bhv.x) + xA.x;
                float v1 = gam * (acc[mi][nj][1] + rsA * bhv.y) + xA.y;
                float v2 = gam * (acc[mi][nj][2] + rsB * bhv.x) + xB.x;
                float v3 = gam * (acc[mi][nj][3] + rsB * bhv.y) + xB.y;
                acc[mi][nj][0] = v0; acc[mi][nj][1] = v1;
                acc[mi][nj][2] = v2; acc[mi][nj][3] = v3;
                sA += v0 + v1; qA += v0 * v0 + v1 * v1;
                sB += v2 + v3; qB += v2 * v2 + v3 * v3;
            }
            #pragma unroll
            for (int o = 1; o <= 2; o <<= 1) {
                sA += __shfl_xor_sync(0xffffffffu, sA, o);
                qA += __shfl_xor_sync(0xffffffffu, qA, o);
                sB += __shfl_xor_sync(0xffffffffu, sB, o);
                qB += __shfl_xor_sync(0xffffffffu, qB, o);
            }
            if (t == 0) {
                sp[(ng * 64 + rA) * 2]     = sA;
                sp[(ng * 64 + rA) * 2 + 1] = qA;
                sp[(ng * 64 + rB) * 2]     = sB;
                sp[(ng * 64 + rB) * 2 + 1] = qB;
            }
        }
    }
    __syncthreads();
    if (tid < 64) {
        float s = 0.f, q = 0.f;
        #pragma unroll
        for (int n = 0; n < 8; n++) {
            s += sp[(n * 64 + tid) * 2];
            q += sp[(n * 64 + tid) * 2 + 1];
        }
        float mean = s * (1.f / SDIM);
        float var  = q * (1.f / SDIM) - mean * mean;
        stats[2 * tid]     = mean;
        stats[2 * tid + 1] = rsqrtf(var + 1e-6f);
    }
    __syncthreads();
    // normalize in regs -> out1h (over Xt region)
    {
        __half2* o2 = (__half2*)Xt;
        #pragma unroll
        for (int mi = 0; mi < 2; mi++) {
            int rA = mg * 32 + mi * 16 + g, rB = rA + 8;
            float mA = stats[2 * rA], vA = stats[2 * rA + 1];
            float mB = stats[2 * rB], vB = stats[2 * rB + 1];
            #pragma unroll
            for (int nj = 0; nj < 8; nj++) {
                int c0 = ng * 64 + nj * 8 + 2 * t;
                float2 gv = *(const float2*)(ln1g + c0);
                float2 bv = *(const float2*)(ln1b + c0);
                o2[rA * 260 + (c0 >> 1)] = __floats2half2_rn(
                    (acc[mi][nj][0] - mA) * vA * gv.x + bv.x,
                    (acc[mi][nj][1] - mA) * vA * gv.y + bv.y);
                o2[rB * 260 + (c0 >> 1)] = __floats2half2_rn(
                    (acc[mi][nj][2] - mB) * vB * gv.x + bv.x,
                    (acc[mi][nj][3] - mB) * vB * gv.y + bv.y);
            }
        }
    }
    __syncthreads();

    // ---- GEMM5: Y = out1 @ Wsn ----
    #pragma unroll
    for (int mi = 0; mi < 2; mi++)
        #pragma unroll
        for (int nj = 0; nj < 8; nj++)
            #pragma unroll
            for (int c = 0; c < 4; c++) acc[mi][nj][c] = 0.f;
    gemm_half(acc, Xtu, g_wsnH, mg, ng, g, t);

    // ---- epilogue 2: y = relu(acc/sigma); LN2 stats ----
    {
        float invsig = g_inv_sigma;
        #pragma unroll
        for (int mi = 0; mi < 2; mi++) {
            int rA = mg * 32 + mi * 16 + g, rB = rA + 8;
            float sA = 0.f, qA = 0.f, sB = 0.f, qB = 0.f;
            #pragma unroll
            for (int nj = 0; nj < 8; nj++) {
                float v0 = fmaxf(acc[mi][nj][0] * invsig, 0.f);
                float v1 = fmaxf(acc[mi][nj][1] * invsig, 0.f);
                float v2 = fmaxf(acc[mi][nj][2] * invsig, 0.f);
                float v3 = fmaxf(acc[mi][nj][3] * invsig, 0.f);
                acc[mi][nj][0] = v0; acc[mi][nj][1] = v1;
                acc[mi][nj][2] = v2; acc[mi][nj][3] = v3;
                sA += v0 + v1; qA += v0 * v0 + v1 * v1;
                sB += v2 + v3; qB += v2 * v2 + v3 * v3;
            }
            #pragma unroll
            for (int o = 1; o <= 2; o <<= 1) {
                sA += __shfl_xor_sync(0xffffffffu, sA, o);
                qA += __shfl_xor_sync(0xffffffffu, qA, o);
                sB += __shfl_xor_sync(0xffffffffu, sB, o);
                qB += __shfl_xor_sync(0xffffffffu, qB, o);
            }
            if (t == 0) {
                sp[(ng * 64 + rA) * 2]     = sA;
                sp[(ng * 64 + rA) * 2 + 1] = qA;
                sp[(ng * 64 + rB) * 2]     = sB;
                sp[(ng * 64 + rB) * 2 + 1] = qB;
            }
        }
    }
    __syncthreads();
    if (tid < 64) {
        float s = 0.f, q = 0.f;
        #pragma unroll
        for (int n = 0; n < 8; n++) {
            s += sp[(n * 64 + tid) * 2];
            q += sp[(n * 64 + tid) * 2 + 1];
        }
        float mean = s * (1.f / SDIM);
        float var  = q * (1.f / SDIM) - mean * mean;
        stats[2 * tid]     = mean;
        stats[2 * tid + 1] = rsqrtf(var + 1e-6f);
    }
    __syncthreads();
    // LN2 normalize -> gmem (float2, full 32B sectors)
    {
        #pragma unroll
        for (int mi = 0; mi < 2; mi++) {
            int rA = mg * 32 + mi * 16 + g, rB = rA + 8;
            float mA = stats[2 * rA], vA = stats[2 * rA + 1];
            float mB = stats[2 * rB], vB = stats[2 * rB + 1];
            #pragma unroll
            for (int nj = 0; nj < 8; nj++) {
                int c0 = ng * 64 + nj * 8 + 2 * t;
                float2 gv = *(const float2*)(ln2g + c0);
                float2 bv = *(const float2*)(ln2b + c0);
                float2 oA, oB;
                oA.x = (acc[mi][nj][0] - mA) * vA * gv.x + bv.x;
                oA.y = (acc[mi][nj][1] - mA) * vA * gv.y + bv.y;
                oB.x = (acc[mi][nj][2] - mB) * vB * gv.x + bv.x;
                oB.y = (acc[mi][nj][3] - mB) * vB * gv.y + bv.y;
                *(float2*)(out + base + (size_t)rA * SDIM + c0) = oA;
                *(float2*)(out + base + (size_t)rB * SDIM + c0) = oB;
            }
        }
    }
}

// ---------------------------------------------------------------------------
extern "C" void kernel_launch(void* const* d_in, const int* in_sizes, int n_in,
                              void* d_out, int out_size) {
    (void)in_sizes; (void)n_in; (void)out_size;
    const float* x    = (const float*)d_in[0];
    const float* wf   = (const float*)d_in[1];
    const float* bf   = (const float*)d_in[2];
    const float* wg   = (const float*)d_in[3];
    const float* bg   = (const float*)d_in[4];
    const float* wh   = (const float*)d_in[5];
    const float* bh   = (const float*)d_in[6];
    const float* gam  = (const float*)d_in[7];
    const float* ln1g = (const float*)d_in[8];
    const float* ln1b = (const float*)d_in[9];
    const float* wsn  = (const float*)d_in[10];
    const float* usn  = (const float*)d_in[11];
    const float* ln2g = (const float*)d_in[12];
    const float* ln2b = (const float*)d_in[13];
    float* out = (float*)d_out;

    init_kernel<<<513, 512>>>(wf, wg, wh, wsn, usn);

    cudaFuncSetAttribute(fused_kernel, cudaFuncAttributeMaxDynamicSharedMemorySize, SM_BYTES);
    fused_kernel<<<1024, 512, SM_BYTES>>>(x, bf, bg, bh, gam,
                                          ln1g, ln1b, ln2g, ln2b, out);
}

// round 14
// speedup vs baseline: 1.7965x; 1.0120x over previous
#include <cuda_runtime.h>
#include <cuda_fp16.h>

#define SDIM 512

// SMEM layout (half-element offsets unless noted)
#define XRM_H 0            // 64 x 520 halves  (X row-major -> AX)
#define XT_H  33280        // 512 x 72 halves  (X transposed -> out1h)
#define FG_H  70144        // 64 x 136 halves
#define ATT_H 78848        // 64 x 72 halves
// float offsets (in floats from smem base)
#define SP_F  41728        // stats partials: (ng*64+row)*2, 1024 floats
#define RS_F  42752        // rowsum 64
#define ST_F  42816        // stats 128
#define SM_BYTES (42944 * 4)

__device__ float g_inv_sigma;
__device__ __align__(16) __half g_whH [262144];
__device__ __align__(16) __half g_wsnH[262144];
__device__ __align__(16) __half g_fgH [65536];

__device__ __forceinline__ void mma16(float* c,
                                      unsigned a0, unsigned a1, unsigned a2, unsigned a3,
                                      unsigned b0, unsigned b1) {
    asm volatile(
        "mma.sync.aligned.m16n8k16.row.col.f32.f16.f16.f32 "
        "{%0,%1,%2,%3}, {%4,%5,%6,%7}, {%8,%9}, {%0,%1,%2,%3};\n"
        : "+f"(c[0]), "+f"(c[1]), "+f"(c[2]), "+f"(c[3])
        : "r"(a0), "r"(a1), "r"(a2), "r"(a3), "r"(b0), "r"(b1));
}

// ---------------------------------------------------------------------------
// init: blocks 0..511 pack fp16 weights (fragment order); block 512 = sigma.
// ---------------------------------------------------------------------------
__global__ __launch_bounds__(512)
void init_kernel(const float* __restrict__ wf, const float* __restrict__ wg,
                 const float* __restrict__ wh, const float* __restrict__ wsn,
                 const float* __restrict__ usn) {
    if (blockIdx.x < 512) {
        int i = blockIdx.x * 512 + threadIdx.x;        // 0..262143
        {
            int j2 = i & 1, j = (i >> 1) & 3, lane = (i >> 3) & 31;
            int s = (i >> 8) & 3, ng = (i >> 10) & 7, ks = i >> 13;
            int r = s >> 1, h = s & 1;
            int col = ng * 64 + (h * 4 + j) * 8 + (lane >> 2);
            int k = ks * 16 + (lane & 3) * 2 + r * 8 + j2;
            g_whH [i] = __float2half_rn(wh [(size_t)k * SDIM + col]);
            g_wsnH[i] = __float2half_rn(wsn[(size_t)k * SDIM + col]);
        }
        if (i < 65536) {
            int j2 = i & 1, j = (i >> 1) & 3, lane = (i >> 3) & 31;
            int r = (i >> 8) & 1, ng = (i >> 9) & 3, ks = i >> 11;
            int col = ng * 32 + j * 8 + (lane >> 2);
            int k = ks * 16 + (lane & 3) * 2 + r * 8 + j2;
            g_fgH[i] = __float2half_rn(col < 64 ? wf[(size_t)k * 64 + col]
                                                : wg[(size_t)k * 64 + col - 64]);
        }
        return;
    }
    // ---- sigma ----
    __shared__ float us[512];
    __shared__ float vs[512];
    __shared__ float red[17];
    int tid = threadIdx.x, wid = tid >> 5, lane = tid & 31;
    us[tid] = usn[tid];
    __syncthreads();

    float q = 0.f;
    for (int rr = 0; rr < 32; rr++) {
        int row = wid * 32 + rr;
        const float4* wr = (const float4*)(wsn + (size_t)row * SDIM);
        const float4* ur = (const float4*)us;
        float s = 0.f;
        #pragma unroll
        for (int i = 0; i < 4; i++) {
            float4 w = wr[lane + i * 32], u = ur[lane + i * 32];
            s += w.x * u.x + w.y * u.y + w.z * u.z + w.w * u.w;
        }
        #pragma unroll
        for (int o = 16; o; o >>= 1) s += __shfl_xor_sync(0xffffffffu, s, o);
        if (lane == 0) { vs[row] = s; q += s * s; }
    }
    if (lane == 0) red[wid] = q;
    __syncthreads();
    if (tid == 0) {
        float z = 0.f;
        for (int i = 0; i < 16; i++) z += red[i];
        red[16] = 1.f / (sqrtf(z) + 1e-12f);
    }
    __syncthreads();
    float inv_nv = red[16];
    __syncthreads();

    float t0 = 0.f, t1 = 0.f, t2 = 0.f, t3 = 0.f;
    for (int i = 0; i < SDIM; i += 4) {
        t0 += vs[i + 0] * wsn[(size_t)(i + 0) * SDIM + tid];
        t1 += vs[i + 1] * wsn[(size_t)(i + 1) * SDIM + tid];
        t2 += vs[i + 2] * wsn[(size_t)(i + 2) * SDIM + tid];
        t3 += vs[i + 3] * wsn[(size_t)(i + 3) * SDIM + tid];
    }
    float tj = ((t0 + t1) + (t2 + t3)) * inv_nv;
    float q2 = tj * tj;
    #pragma unroll
    for (int o = 16; o; o >>= 1) q2 += __shfl_xor_sync(0xffffffffu, q2, o);
    if (lane == 0) red[wid] = q2;
    __syncthreads();
    if (tid == 0) {
        float z = 0.f;
        for (int i = 0; i < 16; i++) z += red[i];
        float nt = sqrtf(z);
        g_inv_sigma = (nt + 1e-12f) / z;
    }
}

// ---------------------------------------------------------------------------
// Streaming fp16 GEMM mainloop with B-register double buffer.
// acc[2][8][4] += A(64x512 row-major halves, stride 260 words) @ Wpacked.
// ---------------------------------------------------------------------------
__device__ __forceinline__ void gemm_half(float (&acc)[2][8][4],
                                          const unsigned* __restrict__ Au,
                                          const __half* __restrict__ WH,
                                          int mg, int ng, int g, int t) {
    const uint4* wp = (const uint4*)WH + (size_t)ng * 128 + (unsigned)(g * 4 + t);
    uint4 B0 = wp[0], B1 = wp[32], B2 = wp[64], B3 = wp[96];
    #pragma unroll 2
    for (int ks = 0; ks < 32; ks++) {
        uint4 N0, N1, N2, N3;
        if (ks + 1 < 32) {
            const uint4* p = wp + (size_t)(ks + 1) * 1024;
            N0 = p[0]; N1 = p[32]; N2 = p[64]; N3 = p[96];
        }
        unsigned b0[8] = {B0.x, B0.y, B0.z, B0.w, B1.x, B1.y, B1.z, B1.w};
        unsigned b1[8] = {B2.x, B2.y, B2.z, B2.w, B3.x, B3.y, B3.z, B3.w};
        int kw = ks * 8;
        #pragma unroll
        for (int mi = 0; mi < 2; mi++) {
            int r = mg * 32 + mi * 16 + g;
            unsigned a0 = Au[r * 260 + kw + t];
            unsigned a1 = Au[(r + 8) * 260 + kw + t];
            unsigned a2 = Au[r * 260 + kw + 4 + t];
            unsigned a3 = Au[(r + 8) * 260 + kw + 4 + t];
            #pragma unroll
            for (int nj = 0; nj < 8; nj++)
                mma16(acc[mi][nj], a0, a1, a2, a3, b0[nj], b1[nj]);
        }
        B0 = N0; B1 = N1; B2 = N2; B3 = N3;
    }
}

// ---------------------------------------------------------------------------
extern __shared__ char smch[];

__global__ __launch_bounds__(512, 1)
void fused_kernel(const float* __restrict__ x,
                  const float* __restrict__ bf, const float* __restrict__ bg,
                  const float* __restrict__ bh,
                  const float* __restrict__ gamma,
                  const float* __restrict__ ln1g, const float* __restrict__ ln1b,
                  const float* __restrict__ ln2g, const float* __restrict__ ln2b,
                  float* __restrict__ out) {
    __half* Xrm  = (__half*)smch;            // X row-major -> AX
    __half* Xt   = (__half*)smch + XT_H;     // X transposed -> out1h
    __half* FGh  = (__half*)smch + FG_H;
    __half* ATTh = (__half*)smch + ATT_H;
    float* sp     = (float*)smch + SP_F;
    float* rowsum = (float*)smch + RS_F;
    float* stats  = (float*)smch + ST_F;

    const unsigned* Xu   = (const unsigned*)Xrm;
    const unsigned* Xtu  = (const unsigned*)Xt;
    const unsigned* FGu  = (const unsigned*)FGh;
    const unsigned* ATTu = (const unsigned*)ATTh;

    const int tid  = threadIdx.x;
    const int wid  = tid >> 5;
    const int lane = tid & 31;
    const int g    = lane >> 2;
    const int t    = lane & 3;
    const size_t base = (size_t)blockIdx.x * (64 * SDIM);

    // ---- load X: row-major half + transposed half ----
    for (int i = tid; i < 8192; i += 512) {
        float4 v = ((const float4*)(x + base))[i];
        int r = i >> 7;
        int c = (i & 127) << 2;
        __half h0 = __float2half_rn(v.x), h1 = __float2half_rn(v.y);
        __half h2 = __float2half_rn(v.z), h3 = __float2half_rn(v.w);
        __half2* w2 = (__half2*)Xrm + r * 260 + (c >> 1);
        w2[0] = __halves2half2(h0, h1);
        w2[1] = __halves2half2(h2, h3);
        Xt[(c + 0) * 72 + r] = h0;
        Xt[(c + 1) * 72 + r] = h1;
        Xt[(c + 2) * 72 + r] = h2;
        Xt[(c + 3) * 72 + r] = h3;
    }
    __syncthreads();

    // ---- GEMM1: [F|G] = X @ [Wf|Wg] + bias  (B prefetched) ----
    {
        const int mg1 = wid & 3;
        const int ng1 = wid >> 2;
        const uint4* fgp = (const uint4*)g_fgH + (size_t)ng1 * 64 + lane;
        float acc1[4][4];
        #pragma unroll
        for (int nj = 0; nj < 4; nj++)
            #pragma unroll
            for (int c = 0; c < 4; c++) acc1[nj][c] = 0.f;

        const int rA = mg1 * 16 + g;
        uint4 FB0 = fgp[0], FB1 = fgp[32];
        #pragma unroll 2
        for (int ks = 0; ks < 32; ks++) {
            uint4 N0, N1;
            if (ks + 1 < 32) {
                const uint4* p = fgp + (size_t)(ks + 1) * 256;
                N0 = p[0]; N1 = p[32];
            }
            unsigned b0[4] = {FB0.x, FB0.y, FB0.z, FB0.w};
            unsigned b1[4] = {FB1.x, FB1.y, FB1.z, FB1.w};
            int kw = ks * 8;
            unsigned a0 = Xu[rA * 260 + kw + t];
            unsigned a1 = Xu[(rA + 8) * 260 + kw + t];
            unsigned a2 = Xu[rA * 260 + kw + 4 + t];
            unsigned a3 = Xu[(rA + 8) * 260 + kw + 4 + t];
            #pragma unroll
            for (int nj = 0; nj < 4; nj++)
                mma16(acc1[nj], a0, a1, a2, a3, b0[nj], b1[nj]);
            FB0 = N0; FB1 = N1;
        }
        #pragma unroll
        for (int nj = 0; nj < 4; nj++) {
            int cg = ng1 * 32 + nj * 8 + 2 * t;
            float bias0 = (cg < 64) ? bf[cg] : bg[cg - 64];
            float bias1 = (cg + 1 < 64) ? bf[cg + 1] : bg[cg + 1 - 64];
            ((__half2*)FGh)[rA * 68 + (cg >> 1)] =
                __floats2half2_rn(acc1[nj][0] + bias0, acc1[nj][1] + bias1);
            ((__half2*)FGh)[(rA + 8) * 68 + (cg >> 1)] =
                __floats2half2_rn(acc1[nj][2] + bias0, acc1[nj][3] + bias1);
        }
    }
    __syncthreads();

    const int mhalf = wid >> 3;
    const int n8    = (wid & 7) * 8;

    // ---- GEMM2: ATT = sigmoid(F @ G^T) ----
    {
        float acc2[2][4];
        #pragma unroll
        for (int mi = 0; mi < 2; mi++)
            #pragma unroll
            for (int c = 0; c < 4; c++) acc2[mi][c] = 0.f;

        unsigned gb0[4], gb1[4];
        #pragma unroll
        for (int ks = 0; ks < 4; ks++) {
            gb0[ks] = FGu[(n8 + g) * 68 + 32 + ks * 8 + t];
            gb1[ks] = FGu[(n8 + g) * 68 + 32 + ks * 8 + 4 + t];
        }
        #pragma unroll
        for (int ks = 0; ks < 4; ks++) {
            int kw = ks * 8;
            #pragma unroll
            for (int mi = 0; mi < 2; mi++) {
                int r = (mhalf * 2 + mi) * 16 + g;
                unsigned a0 = FGu[r * 68 + kw + t];
                unsigned a1 = FGu[(r + 8) * 68 + kw + t];
                unsigned a2 = FGu[r * 68 + kw + 4 + t];
                unsigned a3 = FGu[(r + 8) * 68 + kw + 4 + t];
                mma16(acc2[mi], a0, a1, a2, a3, gb0[ks], gb1[ks]);
            }
        }
        #pragma unroll
        for (int mi = 0; mi < 2; mi++) {
            int r = (mhalf * 2 + mi) * 16 + g;
            float s0 = 1.f / (1.f + __expf(-acc2[mi][0]));
            float s1 = 1.f / (1.f + __expf(-acc2[mi][1]));
            float s2 = 1.f / (1.f + __expf(-acc2[mi][2]));
            float s3 = 1.f / (1.f + __expf(-acc2[mi][3]));
            ((__half2*)ATTh)[r * 36 + (n8 >> 1) + t]       = __floats2half2_rn(s0, s1);
            ((__half2*)ATTh)[(r + 8) * 36 + (n8 >> 1) + t] = __floats2half2_rn(s2, s3);
        }
    }
    __syncthreads();

    if (tid < 64) {
        const __half2* ap = (const __half2*)(ATTh + tid * 72);
        float s = 0.f;
        #pragma unroll 8
        for (int v = 0; v < 32; v++) {
            float2 f = __half22float2(ap[v]);
            s += f.x + f.y;
        }
        rowsum[tid] = s;
    }

    // ---- GEMM3: AX = ATT @ X (B from Xt; overwrite Xrm; no inner barriers) ----
    {
        unsigned aA[2][4][4];
        #pragma unroll
        for (int mi = 0; mi < 2; mi++) {
            int r = (mhalf * 2 + mi) * 16 + g;
            #pragma unroll
            for (int ks = 0; ks < 4; ks++) {
                int kw = ks * 8;
                aA[mi][ks][0] = ATTu[r * 36 + kw + t];
                aA[mi][ks][1] = ATTu[(r + 8) * 36 + kw + t];
                aA[mi][ks][2] = ATTu[r * 36 + kw + 4 + t];
                aA[mi][ks][3] = ATTu[(r + 8) * 36 + kw + 4 + t];
            }
        }
        #pragma unroll 2
        for (int cb = 0; cb < 8; cb++) {
            const int col = cb * 64 + n8 + g;
            const unsigned* XtC = Xtu + col * 36;
            float axc[2][4];
            #pragma unroll
            for (int mi = 0; mi < 2; mi++)
                #pragma unroll
                for (int c = 0; c < 4; c++) axc[mi][c] = 0.f;
            #pragma unroll
            for (int ks = 0; ks < 4; ks++) {
                unsigned b0 = XtC[ks * 8 + t];
                unsigned b1 = XtC[ks * 8 + 4 + t];
                #pragma unroll
                for (int mi = 0; mi < 2; mi++)
                    mma16(axc[mi], aA[mi][ks][0], aA[mi][ks][1],
                          aA[mi][ks][2], aA[mi][ks][3], b0, b1);
            }
            #pragma unroll
            for (int mi = 0; mi < 2; mi++) {
                int r = (mhalf * 2 + mi) * 16 + g;
                int wv = cb * 32 + (n8 >> 1) + t;
                ((__half2*)Xrm)[r * 260 + wv]       = __floats2half2_rn(axc[mi][0], axc[mi][1]);
                ((__half2*)Xrm)[(r + 8) * 260 + wv] = __floats2half2_rn(axc[mi][2], axc[mi][3]);
            }
        }
    }
    __syncthreads();

    // ---- GEMM4: ATTN = AX @ Wh ----
    const int mg = wid & 1;
    const int ng = wid >> 1;
    float acc[2][8][4];
    #pragma unroll
    for (int mi = 0; mi < 2; mi++)
        #pragma unroll
        for (int nj = 0; nj < 8; nj++)
            #pragma unroll
            for (int c = 0; c < 4; c++) acc[mi][nj][c] = 0.f;
    gemm_half(acc, Xu, g_whH, mg, ng, g, t);

    // ---- epilogue 1 in registers: v = gamma*(attn + rowsum*bh) + x ----
    {
        float gam = gamma[0];
        #pragma unroll
        for (int mi = 0; mi < 2; mi++) {
            int rA = mg * 32 + mi * 16 + g, rB = rA + 8;
            float rsA = rowsum[rA], rsB = rowsum[rB];
            float sA = 0.f, qA = 0.f, sB = 0.f, qB = 0.f;
            #pragma unroll
            for (int nj = 0; nj < 8; nj++) {
                int c0 = ng * 64 + nj * 8 + 2 * t;
                float2 bhv = *(const float2*)(bh + c0);
                float2 xA = *(const float2*)(x + base + (size_t)rA * SDIM + c0);
                float2 xB = *(const float2*)(x + base + (size_t)rB * SDIM + c0);
                float v0 = gam * (acc[mi][nj][0] + rsA * bhv.x) + xA.x;
                float v1 = gam * (acc[mi][nj][1] + rsA * bhv.y) + xA.y;
                float v2 = gam * (acc[mi][nj][2] + rsB * bhv.x) + xB.x;
                float v3 = gam * (acc[mi][nj][3] + rsB * bhv.y) + xB.y;
                acc[mi][nj][0] = v0; acc[mi][nj][1] = v1;
                acc[mi][nj][2] = v2; acc[mi][nj][3] = v3;
                sA += v0 + v1; qA += v0 * v0 + v1 * v1;
                sB += v2 + v3; qB += v2 * v2 + v3 * v3;
            }
            #pragma unroll
            for (int o = 1; o <= 2; o <<= 1) {
                sA += __shfl_xor_sync(0xffffffffu, sA, o);
                qA += __shfl_xor_sync(0xffffffffu, qA, o);
                sB += __shfl_xor_sync(0xffffffffu, sB, o);
                qB += __shfl_xor_sync(0xffffffffu, qB, o);
            }
            if (t == 0) {
                sp[(ng * 64 + rA) * 2]     = sA;
                sp[(ng * 64 + rA) * 2 + 1] = qA;
                sp[(ng * 64 + rB) * 2]     = sB;
                sp[(ng * 64 + rB) * 2 + 1] = qB;
            }
        }
    }
    __syncthreads();
    if (tid < 64) {
        float s = 0.f, q = 0.f;
        #pragma unroll
        for (int n = 0; n < 8; n++) {
            s += sp[(n * 64 + tid) * 2];
            q += sp[(n * 64 + tid) * 2 + 1];
        }
        float mean = s * (1.f / SDIM);
        float var  = q * (1.f / SDIM) - mean * mean;
        stats[2 * tid]     = mean;
        stats[2 * tid + 1] = rsqrtf(var + 1e-6f);
    }
    __syncthreads();
    // normalize in regs -> out1h (over Xt region)
    {
        __half2* o2 = (__half2*)Xt;
        #pragma unroll
        for (int mi = 0; mi < 2; mi++) {
            int rA = mg * 32 + mi * 16 + g, rB = rA + 8;
            float mA = stats[2 * rA], vA = stats[2 * rA + 1];
            float mB = stats[2 * rB], vB = stats[2 * rB + 1];
            #pragma unroll
            for (int nj = 0; nj < 8; nj++) {
                int c0 = ng * 64 + nj * 8 + 2 * t;
                float2 gv = *(const float2*)(ln1g + c0);
                float2 bv = *(const float2*)(ln1b + c0);
                o2[rA * 260 + (c0 >> 1)] = __floats2half2_rn(
                    (acc[mi][nj][0] - mA) * vA * gv.x + bv.x,
                    (acc[mi][nj][1] - mA) * vA * gv.y + bv.y);
                o2[rB * 260 + (c0 >> 1)] = __floats2half2_rn(
                    (acc[mi][nj][2] - mB) * vB * gv.x + bv.x,
                    (acc[mi][nj][3] - mB) * vB * gv.y + bv.y);
            }
        }
    }
    __syncthreads();

    // ---- GEMM5: Y = out1 @ Wsn ----
    #pragma unroll
    for (int mi = 0; mi < 2; mi++)
        #pragma unroll
        for (int nj = 0; nj < 8; nj++)
            #pragma unroll
            for (int c = 0; c < 4; c++) acc[mi][nj][c] = 0.f;
    gemm_half(acc, Xtu, g_wsnH, mg, ng, g, t);

    // ---- epilogue 2: y = relu(acc/sigma); LN2 stats ----
    {
        float invsig = g_inv_sigma;
        #pragma unroll
        for (int mi = 0; mi < 2; mi++) {
            int rA = mg * 32 + mi * 16 + g, rB = rA + 8;
            float sA = 0.f, qA = 0.f, sB = 0.f, qB = 0.f;
            #pragma unroll
            for (int nj = 0; nj < 8; nj++) {
                float v0 = fmaxf(acc[mi][nj][0] * invsig, 0.f);
                float v1 = fmaxf(acc[mi][nj][1] * invsig, 0.f);
                float v2 = fmaxf(acc[mi][nj][2] * invsig, 0.f);
                float v3 = fmaxf(acc[mi][nj][3] * invsig, 0.f);
                acc[mi][nj][0] = v0; acc[mi][nj][1] = v1;
                acc[mi][nj][2] = v2; acc[mi][nj][3] = v3;
                sA += v0 + v1; qA += v0 * v0 + v1 * v1;
                sB += v2 + v3; qB += v2 * v2 + v3 * v3;
            }
            #pragma unroll
            for (int o = 1; o <= 2; o <<= 1) {
                sA += __shfl_xor_sync(0xffffffffu, sA, o);
                qA += __shfl_xor_sync(0xffffffffu, qA, o);
                sB += __shfl_xor_sync(0xffffffffu, sB, o);
                qB += __shfl_xor_sync(0xffffffffu, qB, o);
            }
            if (t == 0) {
                sp[(ng * 64 + rA) * 2]     = sA;
                sp[(ng * 64 + rA) * 2 + 1] = qA;
                sp[(ng * 64 + rB) * 2]     = sB;
                sp[(ng * 64 + rB) * 2 + 1] = qB;
            }
        }
    }
    __syncthreads();
    if (tid < 64) {
        float s = 0.f, q = 0.f;
        #pragma unroll
        for (int n = 0; n < 8; n++) {
            s += sp[(n * 64 + tid) * 2];
            q += sp[(n * 64 + tid) * 2 + 1];
        }
        float mean = s * (1.f / SDIM);
        float var  = q * (1.f / SDIM) - mean * mean;
        stats[2 * tid]     = mean;
        stats[2 * tid + 1] = rsqrtf(var + 1e-6f);
    }
    __syncthreads();
    // LN2 normalize -> gmem (float2, full 32B sectors)
    {
        #pragma unroll
        for (int mi = 0; mi < 2; mi++) {
            int rA = mg * 32 + mi * 16 + g, rB = rA + 8;
            float mA = stats[2 * rA], vA = stats[2 * rA + 1];
            float mB = stats[2 * rB], vB = stats[2 * rB + 1];
            #pragma unroll
            for (int nj = 0; nj < 8; nj++) {
                int c0 = ng * 64 + nj * 8 + 2 * t;
                float2 gv = *(const float2*)(ln2g + c0);
                float2 bv = *(const float2*)(ln2b + c0);
                float2 oA, oB;
                oA.x = (acc[mi][nj][0] - mA) * vA * gv.x + bv.x;
                oA.y = (acc[mi][nj][1] - mA) * vA * gv.y + bv.y;
                oB.x = (acc[mi][nj][2] - mB) * vB * gv.x + bv.x;
                oB.y = (acc[mi][nj][3] - mB) * vB * gv.y + bv.y;
                *(float2*)(out + base + (size_t)rA * SDIM + c0) = oA;
                *(float2*)(out + base + (size_t)rB * SDIM + c0) = oB;
            }
        }
    }
}

// ---------------------------------------------------------------------------
extern "C" void kernel_launch(void* const* d_in, const int* in_sizes, int n_in,
                              void* d_out, int out_size) {
    (void)in_sizes; (void)n_in; (void)out_size;
    const float* x    = (const float*)d_in[0];
    const float* wf   = (const float*)d_in[1];
    const float* bf   = (const float*)d_in[2];
    const float* wg   = (const float*)d_in[3];
    const float* bg   = (const float*)d_in[4];
    const float* wh   = (const float*)d_in[5];
    const float* bh   = (const float*)d_in[6];
    const float* gam  = (const float*)d_in[7];
    const float* ln1g = (const float*)d_in[8];
    const float* ln1b = (const float*)d_in[9];
    const float* wsn  = (const float*)d_in[10];
    const float* usn  = (const float*)d_in[11];
    const float* ln2g = (const float*)d_in[12];
    const float* ln2b = (const float*)d_in[13];
    float* out = (float*)d_out;

    init_kernel<<<513, 512>>>(wf, wg, wh, wsn, usn);

    cudaFuncSetAttribute(fused_kernel, cudaFuncAttributeMaxDynamicSharedMemorySize, SM_BYTES);
    fused_kernel<<<1024, 512, SM_BYTES>>>(x, bf, bg, bh, gam,
                                          ln1g, ln1b, ln2g, ln2b, out);
}

// round 16
// speedup vs baseline: 1.8832x; 1.0482x over previous
#include <cuda_runtime.h>
#include <cuda_fp16.h>

#define SDIM 512

// SMEM layout (half-element offsets unless noted)
#define XRM_H 0            // 64 x 520 halves (X row-major -> AX(our rows) -> out1h)
#define FG_H  33280        // 64 x 136 halves
#define ATT_H 41984        // 32 x 72 halves (our rows)
// float offsets
#define SP_F  22144        // 8 ng x 32 rows x 2 = 512 floats
#define RS_F  22656        // 32
#define ST_F  22688        // 64
#define SM_BYTES (22752 * 4)   // 91008 bytes -> 2 CTAs/SM

__device__ float g_inv_sigma;
__device__ __align__(16) __half g_whH [262144];
__device__ __align__(16) __half g_wsnH[262144];
__device__ __align__(16) __half g_fgH [65536];

__device__ __forceinline__ void mma16(float* c,
                                      unsigned a0, unsigned a1, unsigned a2, unsigned a3,
                                      unsigned b0, unsigned b1) {
    asm volatile(
        "mma.sync.aligned.m16n8k16.row.col.f32.f16.f16.f32 "
        "{%0,%1,%2,%3}, {%4,%5,%6,%7}, {%8,%9}, {%0,%1,%2,%3};\n"
        : "+f"(c[0]), "+f"(c[1]), "+f"(c[2]), "+f"(c[3])
        : "r"(a0), "r"(a1), "r"(a2), "r"(a3), "r"(b0), "r"(b1));
}
__device__ __forceinline__ void ldsm2t(unsigned& b0, unsigned& b1, unsigned saddr) {
    asm volatile("ldmatrix.sync.aligned.m8n8.x2.trans.shared.b16 {%0,%1}, [%2];"
                 : "=r"(b0), "=r"(b1) : "r"(saddr));
}

// ---------------------------------------------------------------------------
// init: blocks 0..511 pack fp16 weights (fragment order); block 512 = sigma.
// ---------------------------------------------------------------------------
__global__ __launch_bounds__(512)
void init_kernel(const float* __restrict__ wf, const float* __restrict__ wg,
                 const float* __restrict__ wh, const float* __restrict__ wsn,
                 const float* __restrict__ usn) {
    if (blockIdx.x < 512) {
        int i = blockIdx.x * 512 + threadIdx.x;        // 0..262143
        {
            int j2 = i & 1, j = (i >> 1) & 3, lane = (i >> 3) & 31;
            int s = (i >> 8) & 3, ng = (i >> 10) & 7, ks = i >> 13;
            int r = s >> 1, h = s & 1;
            int col = ng * 64 + (h * 4 + j) * 8 + (lane >> 2);
            int k = ks * 16 + (lane & 3) * 2 + r * 8 + j2;
            g_whH [i] = __float2half_rn(wh [(size_t)k * SDIM + col]);
            g_wsnH[i] = __float2half_rn(wsn[(size_t)k * SDIM + col]);
        }
        if (i < 65536) {
            int j2 = i & 1, j = (i >> 1) & 3, lane = (i >> 3) & 31;
            int r = (i >> 8) & 1, ng = (i >> 9) & 3, ks = i >> 11;
            int col = ng * 32 + j * 8 + (lane >> 2);
            int k = ks * 16 + (lane & 3) * 2 + r * 8 + j2;
            g_fgH[i] = __float2half_rn(col < 64 ? wf[(size_t)k * 64 + col]
                                                : wg[(size_t)k * 64 + col - 64]);
        }
        return;
    }
    // ---- sigma ----
    __shared__ float us[512];
    __shared__ float vs[512];
    __shared__ float red[17];
    int tid = threadIdx.x, wid = tid >> 5, lane = tid & 31;
    us[tid] = usn[tid];
    __syncthreads();

    float q = 0.f;
    for (int rr = 0; rr < 32; rr++) {
        int row = wid * 32 + rr;
        const float4* wr = (const float4*)(wsn + (size_t)row * SDIM);
        const float4* ur = (const float4*)us;
        float s = 0.f;
        #pragma unroll
        for (int i = 0; i < 4; i++) {
            float4 w = wr[lane + i * 32], u = ur[lane + i * 32];
            s += w.x * u.x + w.y * u.y + w.z * u.z + w.w * u.w;
        }
        #pragma unroll
        for (int o = 16; o; o >>= 1) s += __shfl_xor_sync(0xffffffffu, s, o);
        if (lane == 0) { vs[row] = s; q += s * s; }
    }
    if (lane == 0) red[wid] = q;
    __syncthreads();
    if (tid == 0) {
        float z = 0.f;
        for (int i = 0; i < 16; i++) z += red[i];
        red[16] = 1.f / (sqrtf(z) + 1e-12f);
    }
    __syncthreads();
    float inv_nv = red[16];
    __syncthreads();

    float t0 = 0.f, t1 = 0.f, t2 = 0.f, t3 = 0.f;
    for (int i = 0; i < SDIM; i += 4) {
        t0 += vs[i + 0] * wsn[(size_t)(i + 0) * SDIM + tid];
        t1 += vs[i + 1] * wsn[(size_t)(i + 1) * SDIM + tid];
        t2 += vs[i + 2] * wsn[(size_t)(i + 2) * SDIM + tid];
        t3 += vs[i + 3] * wsn[(size_t)(i + 3) * SDIM + tid];
    }
    float tj = ((t0 + t1) + (t2 + t3)) * inv_nv;
    float q2 = tj * tj;
    #pragma unroll
    for (int o = 16; o; o >>= 1) q2 += __shfl_xor_sync(0xffffffffu, q2, o);
    if (lane == 0) red[wid] = q2;
    __syncthreads();
    if (tid == 0) {
        float z = 0.f;
        for (int i = 0; i < 16; i++) z += red[i];
        float nt = sqrtf(z);
        g_inv_sigma = (nt + 1e-12f) / z;
    }
}

// ---------------------------------------------------------------------------
// fp16 streaming GEMM: acc[2][8][4] += A(rows mg*32..+31, stride 260u) @ W.
// ng in 0..7 (64 cols). B register double-buffered.
// ---------------------------------------------------------------------------
__device__ __forceinline__ void gemm_half(float (&acc)[2][8][4],
                                          const unsigned* __restrict__ Au,
                                          const __half* __restrict__ WH,
                                          int mg, int ng, int g, int t) {
    const uint4* wp = (const uint4*)WH + (size_t)ng * 128 + (unsigned)(g * 4 + t);
    uint4 B0 = wp[0], B1 = wp[32], B2 = wp[64], B3 = wp[96];
    #pragma unroll 2
    for (int ks = 0; ks < 32; ks++) {
        uint4 N0, N1, N2, N3;
        if (ks + 1 < 32) {
            const uint4* p = wp + (size_t)(ks + 1) * 1024;
            N0 = p[0]; N1 = p[32]; N2 = p[64]; N3 = p[96];
        }
        unsigned b0[8] = {B0.x, B0.y, B0.z, B0.w, B1.x, B1.y, B1.z, B1.w};
        unsigned b1[8] = {B2.x, B2.y, B2.z, B2.w, B3.x, B3.y, B3.z, B3.w};
        int kw = ks * 8;
        #pragma unroll
        for (int mi = 0; mi < 2; mi++) {
            int r = mg * 32 + mi * 16 + g;
            unsigned a0 = Au[r * 260 + kw + t];
            unsigned a1 = Au[(r + 8) * 260 + kw + t];
            unsigned a2 = Au[r * 260 + kw + 4 + t];
            unsigned a3 = Au[(r + 8) * 260 + kw + 4 + t];
            #pragma unroll
            for (int nj = 0; nj < 8; nj++)
                mma16(acc[mi][nj], a0, a1, a2, a3, b0[nj], b1[nj]);
        }
        B0 = N0; B1 = N1; B2 = N2; B3 = N3;
    }
}

// ---------------------------------------------------------------------------
extern __shared__ char smch[];

__global__ __launch_bounds__(256, 2)
void fused_kernel(const float* __restrict__ x,
                  const float* __restrict__ bf, const float* __restrict__ bg,
                  const float* __restrict__ bh,
                  const float* __restrict__ gamma,
                  const float* __restrict__ ln1g, const float* __restrict__ ln1b,
                  const float* __restrict__ ln2g, const float* __restrict__ ln2b,
                  float* __restrict__ out) {
    __half* Xrm  = (__half*)smch;            // full X -> AX(our rows) -> out1h
    __half* FGh  = (__half*)smch + FG_H;
    __half* ATTh = (__half*)smch + ATT_H;    // our 32 rows
    float* sp     = (float*)smch + SP_F;
    float* rowsum = (float*)smch + RS_F;
    float* stats  = (float*)smch + ST_F;

    const unsigned* Xu   = (const unsigned*)Xrm;
    const unsigned* FGu  = (const unsigned*)FGh;
    const unsigned* ATTu = (const unsigned*)ATTh;

    const int tid  = threadIdx.x;
    const int wid  = tid >> 5;               // 0..7
    const int lane = tid & 31;
    const int g    = lane >> 2;
    const int t    = lane & 3;
    const int half = blockIdx.x & 1;         // which 32-row slice we own
    const size_t base = (size_t)(blockIdx.x >> 1) * (64 * SDIM);

    // ---- load full X -> row-major halves ----
    for (int i = tid; i < 8192; i += 256) {
        float4 v = ((const float4*)(x + base))[i];
        int r = i >> 7;
        int c = (i & 127) << 2;
        __half2* w2 = (__half2*)Xrm + r * 260 + (c >> 1);
        w2[0] = __floats2half2_rn(v.x, v.y);
        w2[1] = __floats2half2_rn(v.z, v.w);
    }
    __syncthreads();

    // ---- GEMM1 (duplicated): [F|G] = X @ [Wf|Wg] + bias, all 64 rows ----
    {
        const int mg1 = wid & 3;             // 16-row groups
        const int ng1 = wid >> 2;            // 0..1, 64 cols each
        const int rA = mg1 * 16 + g;
        float acc1[2][4][4];
        #pragma unroll
        for (int h = 0; h < 2; h++)
            #pragma unroll
            for (int nj = 0; nj < 4; nj++)
                #pragma unroll
                for (int c = 0; c < 4; c++) acc1[h][nj][c] = 0.f;

        const uint4* fg0 = (const uint4*)g_fgH + (size_t)(ng1 * 2) * 64 + lane;
        uint4 C0 = fg0[0],  C1 = fg0[32];    // h=0
        uint4 D0 = fg0[64], D1 = fg0[96];    // h=1
        #pragma unroll 2
        for (int ks = 0; ks < 32; ks++) {
            uint4 nC0, nC1, nD0, nD1;
            if (ks + 1 < 32) {
                const uint4* p = fg0 + (size_t)(ks + 1) * 256;
                nC0 = p[0]; nC1 = p[32]; nD0 = p[64]; nD1 = p[96];
            }
            int kw = ks * 8;
            unsigned a0 = Xu[rA * 260 + kw + t];
            unsigned a1 = Xu[(rA + 8) * 260 + kw + t];
            unsigned a2 = Xu[rA * 260 + kw + 4 + t];
            unsigned a3 = Xu[(rA + 8) * 260 + kw + 4 + t];
            unsigned c0[4] = {C0.x, C0.y, C0.z, C0.w};
            unsigned c1[4] = {C1.x, C1.y, C1.z, C1.w};
            unsigned d0[4] = {D0.x, D0.y, D0.z, D0.w};
            unsigned d1[4] = {D1.x, D1.y, D1.z, D1.w};
            #pragma unroll
            for (int nj = 0; nj < 4; nj++) {
                mma16(acc1[0][nj], a0, a1, a2, a3, c0[nj], c1[nj]);
                mma16(acc1[1][nj], a0, a1, a2, a3, d0[nj], d1[nj]);
            }
            C0 = nC0; C1 = nC1; D0 = nD0; D1 = nD1;
        }
        #pragma unroll
        for (int h = 0; h < 2; h++)
            #pragma unroll
            for (int nj = 0; nj < 4; nj++) {
                int cg = (ng1 * 2 + h) * 32 + nj * 8 + 2 * t;
                float bias0 = (cg < 64) ? bf[cg] : bg[cg - 64];
                float bias1 = (cg + 1 < 64) ? bf[cg + 1] : bg[cg + 1 - 64];
                ((__half2*)FGh)[rA * 68 + (cg >> 1)] =
                    __floats2half2_rn(acc1[h][nj][0] + bias0, acc1[h][nj][1] + bias1);
                ((__half2*)FGh)[(rA + 8) * 68 + (cg >> 1)] =
                    __floats2half2_rn(acc1[h][nj][2] + bias0, acc1[h][nj][3] + bias1);
            }
    }
    __syncthreads();

    // ---- GEMM2: ATT(our 32 rows x 64) = sigmoid(F @ G^T) ----
    {
        const int mh2 = wid & 1;             // local 16-row group
        const int n16 = (wid >> 1) * 16;     // 16-col group
        const int rG = half * 32 + mh2 * 16; // global F row base
        float acc2[2][4];
        #pragma unroll
        for (int nj = 0; nj < 2; nj++)
            #pragma unroll
            for (int c = 0; c < 4; c++) acc2[nj][c] = 0.f;

        unsigned gb0[2][4], gb1[2][4];
        #pragma unroll
        for (int nj = 0; nj < 2; nj++)
            #pragma unroll
            for (int ks = 0; ks < 4; ks++) {
                gb0[nj][ks] = FGu[(n16 + nj * 8 + g) * 68 + 32 + ks * 8 + t];
                gb1[nj][ks] = FGu[(n16 + nj * 8 + g) * 68 + 32 + ks * 8 + 4 + t];
            }
        #pragma unroll
        for (int ks = 0; ks < 4; ks++) {
            int kw = ks * 8;
            unsigned a0 = FGu[(rG + g) * 68 + kw + t];
            unsigned a1 = FGu[(rG + 8 + g) * 68 + kw + t];
            unsigned a2 = FGu[(rG + g) * 68 + kw + 4 + t];
            unsigned a3 = FGu[(rG + 8 + g) * 68 + kw + 4 + t];
            #pragma unroll
            for (int nj = 0; nj < 2; nj++)
                mma16(acc2[nj], a0, a1, a2, a3, gb0[nj][ks], gb1[nj][ks]);
        }
        int rl = mh2 * 16 + g;
        #pragma unroll
        for (int nj = 0; nj < 2; nj++) {
            float s0 = 1.f / (1.f + __expf(-acc2[nj][0]));
            float s1 = 1.f / (1.f + __expf(-acc2[nj][1]));
            float s2 = 1.f / (1.f + __expf(-acc2[nj][2]));
            float s3 = 1.f / (1.f + __expf(-acc2[nj][3]));
            ((__half2*)ATTh)[rl * 36 + (n16 >> 1) + nj * 4 + t]       = __floats2half2_rn(s0, s1);
            ((__half2*)ATTh)[(rl + 8) * 36 + (n16 >> 1) + nj * 4 + t] = __floats2half2_rn(s2, s3);
        }
    }
    __syncthreads();

    if (tid < 32) {
        const __half2* ap = (const __half2*)(ATTh + tid * 72);
        float s = 0.f;
        #pragma unroll 8
        for (int v = 0; v < 32; v++) {
            float2 f = __half22float2(ap[v]);
            s += f.x + f.y;
        }
        rowsum[tid] = s;
    }

    // ---- GEMM3: AX(our rows) = ATT @ X, chunk-wise in place (ldmatrix B) ----
    {
        const int mh3 = wid & 1;
        const int nq  = wid >> 1;            // 0..3, 16 cols of each 64-chunk
        const unsigned xb_s = (unsigned)__cvta_generic_to_shared(Xrm);
        unsigned aA[4][4];
        {
            int rl = mh3 * 16 + g;
            #pragma unroll
            for (int ks = 0; ks < 4; ks++) {
                int kw = ks * 8;
                aA[ks][0] = ATTu[rl * 36 + kw + t];
                aA[ks][1] = ATTu[(rl + 8) * 36 + kw + t];
                aA[ks][2] = ATTu[rl * 36 + kw + 4 + t];
                aA[ks][3] = ATTu[(rl + 8) * 36 + kw + 4 + t];
            }
        }
        for (int cb = 0; cb < 8; cb++) {
            int n0 = cb * 64 + nq * 16;
            float acc3[2][4];
            #pragma unroll
            for (int nj = 0; nj < 2; nj++)
                #pragma unroll
                for (int c = 0; c < 4; c++) acc3[nj][c] = 0.f;
            #pragma unroll
            for (int ks = 0; ks < 4; ks++) {
                #pragma unroll
                for (int nj = 0; nj < 2; nj++) {
                    unsigned b0, b1;
                    unsigned addr = xb_s + (((ks * 16 + (lane & 15)) * 520)
                                          + n0 + nj * 8) * 2;
                    ldsm2t(b0, b1, addr);
                    mma16(acc3[nj], aA[ks][0], aA[ks][1], aA[ks][2], aA[ks][3], b0, b1);
                }
            }
            __syncthreads();   // all B reads of chunk cb complete
            int rg = half * 32 + mh3 * 16 + g;
            #pragma unroll
            for (int nj = 0; nj < 2; nj++) {
                int wv = (n0 >> 1) + nj * 4 + t;
                ((__half2*)Xrm)[rg * 260 + wv]       = __floats2half2_rn(acc3[nj][0], acc3[nj][1]);
                ((__half2*)Xrm)[(rg + 8) * 260 + wv] = __floats2half2_rn(acc3[nj][2], acc3[nj][3]);
            }
        }
    }
    __syncthreads();

    // ---- GEMM4: ATTN = AX @ Wh (our 32 rows) ----
    const int ng = wid;                      // 0..7, 64 cols
    float acc[2][8][4];
    #pragma unroll
    for (int mi = 0; mi < 2; mi++)
        #pragma unroll
        for (int nj = 0; nj < 8; nj++)
            #pragma unroll
            for (int c = 0; c < 4; c++) acc[mi][nj][c] = 0.f;
    gemm_half(acc, Xu, g_whH, half, ng, g, t);

    // ---- epilogue 1 in registers: v = gamma*(attn + rowsum*bh) + x ----
    {
        float gam = gamma[0];
        #pragma unroll
        for (int mi = 0; mi < 2; mi++) {
            int rlA = mi * 16 + g, rlB = rlA + 8;
            int rA = half * 32 + rlA, rB = rA + 8;
            float rsA = rowsum[rlA], rsB = rowsum[rlB];
            float sA = 0.f, qA = 0.f, sB = 0.f, qB = 0.f;
            #pragma unroll
            for (int nj = 0; nj < 8; nj++) {
                int c0 = ng * 64 + nj * 8 + 2 * t;
                float2 bhv = *(const float2*)(bh + c0);
                float2 xA = *(const float2*)(x + base + (size_t)rA * SDIM + c0);
                float2 xB = *(const float2*)(x + base + (size_t)rB * SDIM + c0);
                float v0 = gam * (acc[mi][nj][0] + rsA * bhv.x) + xA.x;
                float v1 = gam * (acc[mi][nj][1] + rsA * bhv.y) + xA.y;
                float v2 = gam * (acc[mi][nj][2] + rsB * bhv.x) + xB.x;
                float v3 = gam * (acc[mi][nj][3] + rsB * bhv.y) + xB.y;
                acc[mi][nj][0] = v0; acc[mi][nj][1] = v1;
                acc[mi][nj][2] = v2; acc[mi][nj][3] = v3;
                sA += v0 + v1; qA += v0 * v0 + v1 * v1;
                sB += v2 + v3; qB += v2 * v2 + v3 * v3;
            }
            #pragma unroll
            for (int o = 1; o <= 2; o <<= 1) {
                sA += __shfl_xor_sync(0xffffffffu, sA, o);
                qA += __shfl_xor_sync(0xffffffffu, qA, o);
                sB += __shfl_xor_sync(0xffffffffu, sB, o);
                qB += __shfl_xor_sync(0xffffffffu, qB, o);
            }
            if (t == 0) {
                sp[(ng * 32 + rlA) * 2]     = sA;
                sp[(ng * 32 + rlA) * 2 + 1] = qA;
                sp[(ng * 32 + rlB) * 2]     = sB;
                sp[(ng * 32 + rlB) * 2 + 1] = qB;
            }
        }
    }
    __syncthreads();
    if (tid < 32) {
        float s = 0.f, q = 0.f;
        #pragma unroll
        for (int n = 0; n < 8; n++) {
            s += sp[(n * 32 + tid) * 2];
            q += sp[(n * 32 + tid) * 2 + 1];
        }
        float mean = s * (1.f / SDIM);
        float var  = q * (1.f / SDIM) - mean * mean;
        stats[2 * tid]     = mean;
        stats[2 * tid + 1] = rsqrtf(var + 1e-6f);
    }
    __syncthreads();
    // LN1 normalize in regs -> out1h into Xrm (our rows)
    {
        __half2* o2 = (__half2*)Xrm;
        #pragma unroll
        for (int mi = 0; mi < 2; mi++) {
            int rlA = mi * 16 + g, rlB = rlA + 8;
            int rA = half * 32 + rlA, rB = rA + 8;
            float mA = stats[2 * rlA], vA = stats[2 * rlA + 1];
            float mB = stats[2 * rlB], vB = stats[2 * rlB + 1];
            #pragma unroll
            for (int nj = 0; nj < 8; nj++) {
                int c0 = ng * 64 + nj * 8 + 2 * t;
                float2 gv = *(const float2*)(ln1g + c0);
                float2 bv = *(const float2*)(ln1b + c0);
                o2[rA * 260 + (c0 >> 1)] = __floats2half2_rn(
                    (acc[mi][nj][0] - mA) * vA * gv.x + bv.x,
                    (acc[mi][nj][1] - mA) * vA * gv.y + bv.y);
                o2[rB * 260 + (c0 >> 1)] = __floats2half2_rn(
                    (acc[mi][nj][2] - mB) * vB * gv.x + bv.x,
                    (acc[mi][nj][3] - mB) * vB * gv.y + bv.y);
            }
        }
    }
    __syncthreads();

    // ---- GEMM5: Y = out1 @ Wsn ----
    #pragma unroll
    for (int mi = 0; mi < 2; mi++)
        #pragma unroll
        for (int nj = 0; nj < 8; nj++)
            #pragma unroll
            for (int c = 0; c < 4; c++) acc[mi][nj][c] = 0.f;
    gemm_half(acc, Xu, g_wsnH, half, ng, g, t);

    // ---- epilogue 2: relu(acc/sigma); LN2 stats ----
    {
        float invsig = g_inv_sigma;
        #pragma unroll
        for (int mi = 0; mi < 2; mi++) {
            int rlA = mi * 16 + g, rlB = rlA + 8;
            float sA = 0.f, qA = 0.f, sB = 0.f, qB = 0.f;
            #pragma unroll
            for (int nj = 0; nj < 8; nj++) {
                float v0 = fmaxf(acc[mi][nj][0] * invsig, 0.f);
                float v1 = fmaxf(acc[mi][nj][1] * invsig, 0.f);
                float v2 = fmaxf(acc[mi][nj][2] * invsig, 0.f);
                float v3 = fmaxf(acc[mi][nj][3] * invsig, 0.f);
                acc[mi][nj][0] = v0; acc[mi][nj][1] = v1;
                acc[mi][nj][2] = v2; acc[mi][nj][3] = v3;
                sA += v0 + v1; qA += v0 * v0 + v1 * v1;
                sB += v2 + v3; qB += v2 * v2 + v3 * v3;
            }
            #pragma unroll
            for (int o = 1; o <= 2; o <<= 1) {
                sA += __shfl_xor_sync(0xffffffffu, sA, o);
                qA += __shfl_xor_sync(0xffffffffu, qA, o);
                sB += __shfl_xor_sync(0xffffffffu, sB, o);
                qB += __shfl_xor_sync(0xffffffffu, qB, o);
            }
            if (t == 0) {
                sp[(ng * 32 + rlA) * 2]     = sA;
                sp[(ng * 32 + rlA) * 2 + 1] = qA;
                sp[(ng * 32 + rlB) * 2]     = sB;
                sp[(ng * 32 + rlB) * 2 + 1] = qB;
            }
        }
    }
    __syncthreads();
    if (tid < 32) {
        float s = 0.f, q = 0.f;
        #pragma unroll
        for (int n = 0; n < 8; n++) {
            s += sp[(n * 32 + tid) * 2];
            q += sp[(n * 32 + tid) * 2 + 1];
        }
        float mean = s * (1.f / SDIM);
        float var  = q * (1.f / SDIM) - mean * mean;
        stats[2 * tid]     = mean;
        stats[2 * tid + 1] = rsqrtf(var + 1e-6f);
    }
    __syncthreads();
    // LN2 normalize -> gmem
    {
        #pragma unroll
        for (int mi = 0; mi < 2; mi++) {
            int rlA = mi * 16 + g, rlB = rlA + 8;
            int rA = half * 32 + rlA, rB = rA + 8;
            float mA = stats[2 * rlA], vA = stats[2 * rlA + 1];
            float mB = stats[2 * rlB], vB = stats[2 * rlB + 1];
            #pragma unroll
            for (int nj = 0; nj < 8; nj++) {
                int c0 = ng * 64 + nj * 8 + 2 * t;
                float2 gv = *(const float2*)(ln2g + c0);
                float2 bv = *(const float2*)(ln2b + c0);
                float2 oA, oB;
                oA.x = (acc[mi][nj][0] - mA) * vA * gv.x + bv.x;
                oA.y = (acc[mi][nj][1] - mA) * vA * gv.y + bv.y;
                oB.x = (acc[mi][nj][2] - mB) * vB * gv.x + bv.x;
                oB.y = (acc[mi][nj][3] - mB) * vB * gv.y + bv.y;
                *(float2*)(out + base + (size_t)rA * SDIM + c0) = oA;
                *(float2*)(out + base + (size_t)rB * SDIM + c0) = oB;
            }
        }
    }
}

// ---------------------------------------------------------------------------
extern "C" void kernel_launch(void* const* d_in, const int* in_sizes, int n_in,
                              void* d_out, int out_size) {
    (void)in_sizes; (void)n_in; (void)out_size;
    const float* x    = (const float*)d_in[0];
    const float* wf   = (const float*)d_in[1];
    const float* bf   = (const float*)d_in[2];
    const float* wg   = (const float*)d_in[3];
    const float* bg   = (const float*)d_in[4];
    const float* wh   = (const float*)d_in[5];
    const float* bh   = (const float*)d_in[6];
    const float* gam  = (const float*)d_in[7];
    const float* ln1g = (const float*)d_in[8];
    const float* ln1b = (const float*)d_in[9];
    const float* wsn  = (const float*)d_in[10];
    const float* usn  = (const float*)d_in[11];
    const float* ln2g = (const float*)d_in[12];
    const float* ln2b = (const float*)d_in[13];
    float* out = (float*)d_out;

    init_kernel<<<513, 512>>>(wf, wg, wh, wsn, usn);

    cudaFuncSetAttribute(fused_kernel, cudaFuncAttributeMaxDynamicSharedMemorySize, SM_BYTES);
    fused_kernel<<<2048, 256, SM_BYTES>>>(x, bf, bg, bh, gam,
                                          ln1g, ln1b, ln2g, ln2b, out);
}